// round 6
// baseline (speedup 1.0000x reference)
#include <cuda_runtime.h>
#include <cuda_bf16.h>
#include <cstdint>
#include <cstddef>

// ---------------------------------------------------------------------------
// Problem constants
// ---------------------------------------------------------------------------
#define S_LEN 16384
#define D_HID 1280
#define H_NUM 16
#define HD_DIM 80
#define WS_WIN 64
#define NW_WIN (S_LEN / WS_WIN)   // 256
#define QKV_N (3 * D_HID)         // 3840
#define KDIM 1280

// GEMM tiling: CTA 128x256, BK=32, 16 warps (2Mx8N), warp tile 64x32
#define BM 128
#define BN 256
#define BK 32
#define STAGES 3
#define KT_ITERS (KDIM / BK)      // 40
#define STAGE_BYTES 49152         // Ah 8K | Al 8K | Bh 16K | Bl 16K
#define GEMM_SMEM (STAGES * STAGE_BYTES)   // 147456

// ---------------------------------------------------------------------------
// Scratch (device globals: allocation-free contract)
// ---------------------------------------------------------------------------
__device__ float g_qkv[(size_t)S_LEN * QKV_N];
__device__ __nv_bfloat16 g_hid_hi[(size_t)S_LEN * D_HID];
__device__ __nv_bfloat16 g_hid_lo[(size_t)S_LEN * D_HID];
__device__ __nv_bfloat16 g_wqkv_hi[(size_t)QKV_N * D_HID];
__device__ __nv_bfloat16 g_wqkv_lo[(size_t)QKV_N * D_HID];
__device__ __nv_bfloat16 g_wproj_hi[(size_t)D_HID * D_HID];
__device__ __nv_bfloat16 g_wproj_lo[(size_t)D_HID * D_HID];
__device__ __nv_bfloat16 g_attn_hi[(size_t)S_LEN * D_HID];
__device__ __nv_bfloat16 g_attn_lo[(size_t)S_LEN * D_HID];

// ---------------------------------------------------------------------------
// PTX helpers (baseline sm_80+ only -- harness targets plain sm_100)
// ---------------------------------------------------------------------------
__device__ __forceinline__ uint32_t smem_u32(const void* p) {
    uint32_t a;
    asm("{ .reg .u64 t; cvta.to.shared.u64 t, %1; cvt.u32.u64 %0, t; }"
        : "=r"(a) : "l"(p));
    return a;
}

#define CP_ASYNC16(smem_addr, gptr) \
    asm volatile("cp.async.cg.shared.global [%0], [%1], 16;\n" \
                 :: "r"(smem_addr), "l"(gptr))
#define CP_ASYNC_COMMIT() asm volatile("cp.async.commit_group;\n" ::: "memory")
#define CP_ASYNC_WAIT1()  asm volatile("cp.async.wait_group 1;\n" ::: "memory")

#define LDSM_X4(r0, r1, r2, r3, addr) \
    asm volatile("ldmatrix.sync.aligned.m8n8.x4.shared.b16 {%0,%1,%2,%3}, [%4];" \
                 : "=r"(r0), "=r"(r1), "=r"(r2), "=r"(r3) : "r"(addr))

#define MMA16816(d, a0, a1, a2, a3, b0, b1) \
    asm volatile("mma.sync.aligned.m16n8k16.row.col.f32.bf16.bf16.f32 " \
                 "{%0,%1,%2,%3}, {%4,%5,%6,%7}, {%8,%9}, {%0,%1,%2,%3};" \
                 : "+f"((d)[0]), "+f"((d)[1]), "+f"((d)[2]), "+f"((d)[3]) \
                 : "r"(a0), "r"(a1), "r"(a2), "r"(a3), "r"(b0), "r"(b1))

// ---------------------------------------------------------------------------
// bf16x3 mma.sync GEMM: C[M, Ntot] = A[M,1280] * B[Ntot,1280]^T + bias
// 512 threads, 16 warps (2M x 8N), warp tile 64x32.
// ---------------------------------------------------------------------------
__global__ void __launch_bounds__(512, 1) gemm_bf16x3(
    const __nv_bfloat16* __restrict__ Ah, const __nv_bfloat16* __restrict__ Al,
    const __nv_bfloat16* __restrict__ Bh, const __nv_bfloat16* __restrict__ Bl,
    const float* __restrict__ bias, float* __restrict__ C, int Ntot)
{
    extern __shared__ char smem[];
    const uint32_t sb = smem_u32(smem);
    const int tid = threadIdx.x;
    const int wid = tid >> 5, lane = tid & 31;
    const int warp_m = wid & 1;        // 0..1 (64-row slabs)
    const int warp_n = wid >> 1;       // 0..7 (32-col slabs)
    const int m0 = blockIdx.y * BM;
    const int n0 = blockIdx.x * BN;

    // ---- per-thread cp.async mapping: 6 chunks of 16B per stage ----
    const __nv_bfloat16* gptr[6];
    uint32_t soff[6];
    #pragma unroll
    for (int t = 0; t < 6; t++) {
        const int idx = tid + t * 512;         // 0..3071
        const __nv_bfloat16* base;
        int row, c;
        uint32_t mbase;
        int r0;
        if (idx < 1024) {                       // A half (Ah, Al)
            const int mat = idx >> 9;
            const int li = idx & 511;
            row = li >> 2; c = li & 3;
            base = mat ? Al : Ah;
            mbase = (uint32_t)(mat * 8192);
            r0 = m0 + row;
        } else {                                // B half (Bh, Bl)
            const int j = idx - 1024;
            const int mat = j >> 10;
            const int li = j & 1023;
            row = li >> 2; c = li & 3;
            base = mat ? Bl : Bh;
            mbase = (uint32_t)(16384 + mat * 16384);
            r0 = n0 + row;
        }
        gptr[t] = base + (size_t)r0 * KDIM + c * 8;
        soff[t] = mbase + (uint32_t)(row * 64 + ((c ^ ((row >> 1) & 3)) << 4));
    }

    // ---- prefetch first STAGES-1 stages ----
    #pragma unroll
    for (int s = 0; s < STAGES - 1; s++) {
        const int kb = s * BK;
        #pragma unroll
        for (int t = 0; t < 6; t++)
            CP_ASYNC16(sb + s * STAGE_BYTES + soff[t], gptr[t] + kb);
        CP_ASYNC_COMMIT();
    }

    // ---- ldmatrix base offsets (chunk=csel), fully swizzled ----
    const int row_in = lane & 15;
    const int csel = lane >> 4;                 // chunk bit0
    uint32_t aOff[4], bOff[2];
    #pragma unroll
    for (int fm = 0; fm < 4; fm++) {
        const int r = warp_m * 64 + fm * 16 + row_in;
        aOff[fm] = (uint32_t)(r * 64 + (((uint32_t)csel ^ ((r >> 1) & 3)) << 4));
    }
    #pragma unroll
    for (int bt = 0; bt < 2; bt++) {
        const int r = warp_n * 32 + bt * 16 + row_in;
        bOff[bt] = (uint32_t)(16384 + r * 64 + (((uint32_t)csel ^ ((r >> 1) & 3)) << 4));
    }

    float acc[4][4][4];
    #pragma unroll
    for (int i = 0; i < 4; i++)
        #pragma unroll
        for (int j = 0; j < 4; j++)
            #pragma unroll
            for (int k = 0; k < 4; k++) acc[i][j][k] = 0.f;

    // ---- main loop ----
    for (int kt = 0; kt < KT_ITERS; kt++) {
        CP_ASYNC_WAIT1();
        __syncthreads();

        if (kt + STAGES - 1 < KT_ITERS) {
            const int s = (kt + STAGES - 1) % STAGES;
            const int kb = (kt + STAGES - 1) * BK;
            #pragma unroll
            for (int t = 0; t < 6; t++)
                CP_ASYNC16(sb + s * STAGE_BYTES + soff[t], gptr[t] + kb);
        }
        CP_ASYNC_COMMIT();

        const uint32_t stg = sb + (kt % STAGES) * STAGE_BYTES;

        #pragma unroll
        for (int kk = 0; kk < 2; kk++) {
            const uint32_t kx = (uint32_t)(kk * 0x20);   // chunk bit1 -> addr bit5

            // B fragments: 4 n8 frags x {hi, lo}
            uint32_t bh[4][2], bl[4][2];
            #pragma unroll
            for (int bt = 0; bt < 2; bt++) {
                const uint32_t ad = stg + (bOff[bt] ^ kx);
                uint32_t r0, r1, r2, r3;
                LDSM_X4(r0, r1, r2, r3, ad);
                bh[bt * 2 + 0][0] = r0; bh[bt * 2 + 1][0] = r1;
                bh[bt * 2 + 0][1] = r2; bh[bt * 2 + 1][1] = r3;
                LDSM_X4(r0, r1, r2, r3, ad + 16384);
                bl[bt * 2 + 0][0] = r0; bl[bt * 2 + 1][0] = r1;
                bl[bt * 2 + 0][1] = r2; bl[bt * 2 + 1][1] = r3;
            }

            #pragma unroll
            for (int fm = 0; fm < 4; fm++) {
                const uint32_t ad = stg + (aOff[fm] ^ kx);
                uint32_t ah0, ah1, ah2, ah3, al0, al1, al2, al3;
                LDSM_X4(ah0, ah1, ah2, ah3, ad);
                LDSM_X4(al0, al1, al2, al3, ad + 8192);
                // term-major within fm: 4 independent accs per term
                #pragma unroll
                for (int fn = 0; fn < 4; fn++)
                    MMA16816(acc[fm][fn], ah0, ah1, ah2, ah3, bh[fn][0], bh[fn][1]);
                #pragma unroll
                for (int fn = 0; fn < 4; fn++)
                    MMA16816(acc[fm][fn], ah0, ah1, ah2, ah3, bl[fn][0], bl[fn][1]);
                #pragma unroll
                for (int fn = 0; fn < 4; fn++)
                    MMA16816(acc[fm][fn], al0, al1, al2, al3, bh[fn][0], bh[fn][1]);
            }
        }
    }

    // ---- epilogue: bias + coalesced STG.64 ----
    const int tr = lane >> 2;
    const int tc = (lane & 3) * 2;
    const int r_base = m0 + warp_m * 64;
    const int c_base = n0 + warp_n * 32;
    #pragma unroll
    for (int fn = 0; fn < 4; fn++) {
        const int col = c_base + fn * 8 + tc;
        const float2 bb = *(const float2*)&bias[col];
        #pragma unroll
        for (int fm = 0; fm < 4; fm++) {
            const int row0 = r_base + fm * 16 + tr;
            float2 v0, v1;
            v0.x = acc[fm][fn][0] + bb.x; v0.y = acc[fm][fn][1] + bb.y;
            v1.x = acc[fm][fn][2] + bb.x; v1.y = acc[fm][fn][3] + bb.y;
            *(float2*)&C[(size_t)row0 * Ntot + col] = v0;
            *(float2*)&C[(size_t)(row0 + 8) * Ntot + col] = v1;
        }
    }
}

// ---------------------------------------------------------------------------
// fp32 -> bf16 (hi, lo) split
// ---------------------------------------------------------------------------
__global__ void split_bf16(const float* __restrict__ src,
                           __nv_bfloat16* __restrict__ hi,
                           __nv_bfloat16* __restrict__ lo, int n)
{
    int i = blockIdx.x * blockDim.x + threadIdx.x;
    if (i < n) {
        float x = src[i];
        __nv_bfloat16 h = __float2bfloat16(x);
        hi[i] = h;
        lo[i] = __float2bfloat16(x - __bfloat162float(h));
    }
}

// ---------------------------------------------------------------------------
// Windowed attention (fp32), one block per (window, head).
// Row stride 84 floats: 16B-aligned rows, conflict-free LDS.128.
// ---------------------------------------------------------------------------
#define Q_LD 84
#define P_LD 65

__global__ void __launch_bounds__(256) attn_kernel(
    const float* __restrict__ qkv,
    const float* __restrict__ mask,
    const float* __restrict__ cosv,
    const float* __restrict__ sinv,
    __nv_bfloat16* __restrict__ out_hi,
    __nv_bfloat16* __restrict__ out_lo)
{
    extern __shared__ float sm[];
    float* qs = sm;
    float* ks = qs + 64 * Q_LD;
    float* vs = ks + 64 * Q_LD;
    float* ps = vs + 64 * Q_LD;

    const int w = blockIdx.x >> 4;
    const int h = blockIdx.x & 15;
    const int tid = threadIdx.x;

    // phase 1: streaming float4 copy (q, k, v raw)
    for (int u = tid; u < 64 * 20 * 3; u += 256) {
        const int mat = u / (64 * 20);          // 0:q 1:k 2:v
        const int li = u % (64 * 20);
        const int p = li / 20, c4 = li % 20;
        const int s = w * WS_WIN + p;
        const float4 v = *(const float4*)&qkv[(size_t)s * QKV_N + mat * D_HID + h * HD_DIM + c4 * 4];
        float* dst = (mat == 0 ? qs : mat == 1 ? ks : vs) + p * Q_LD + c4 * 4;
        *(float4*)dst = v;
    }
    __syncthreads();

    // phase 2: in-smem RoPE on q, k (pairs d, d+40)
    for (int u = tid; u < 64 * 40; u += 256) {
        const int p = u / 40, d = u % 40;
        const int s = w * WS_WIN + p;
        const float c0 = cosv[s * HD_DIM + d];
        const float c1 = cosv[s * HD_DIM + d + 40];
        const float s0 = sinv[s * HD_DIM + d];
        const float s1 = sinv[s * HD_DIM + d + 40];

        float* qp = &qs[p * Q_LD];
        const float q0 = qp[d], q1 = qp[d + 40];
        qp[d]      = q0 * c0 - q1 * s0;
        qp[d + 40] = q1 * c1 + q0 * s1;

        float* kp = &ks[p * Q_LD];
        const float k0 = kp[d], k1 = kp[d + 40];
        kp[d]      = k0 * c0 - k1 * s0;
        kp[d + 40] = k1 * c1 + k0 * s1;
    }
    __syncthreads();

    const float scale = 0.1118033988749895f;
    const int warp = tid >> 5, lane = tid & 31;
    const float* mrow_base = mask + (size_t)w * (WS_WIN * WS_WIN);

    #pragma unroll
    for (int i = 0; i < 8; i++) {
        const int r = warp * 8 + i;
        float v0 = 0.f, v1 = 0.f;
        const float4* q4  = (const float4*)&qs[r * Q_LD];
        const float4* k04 = (const float4*)&ks[lane * Q_LD];
        const float4* k14 = (const float4*)&ks[(lane + 32) * Q_LD];
        #pragma unroll
        for (int dd = 0; dd < 20; dd++) {
            const float4 q = q4[dd];
            const float4 a = k04[dd];
            const float4 b = k14[dd];
            v0 = fmaf(q.x, a.x, v0); v0 = fmaf(q.y, a.y, v0);
            v0 = fmaf(q.z, a.z, v0); v0 = fmaf(q.w, a.w, v0);
            v1 = fmaf(q.x, b.x, v1); v1 = fmaf(q.y, b.y, v1);
            v1 = fmaf(q.z, b.z, v1); v1 = fmaf(q.w, b.w, v1);
        }
        v0 = v0 * scale + mrow_base[r * WS_WIN + lane];
        v1 = v1 * scale + mrow_base[r * WS_WIN + lane + 32];

        float mx = fmaxf(v0, v1);
        #pragma unroll
        for (int o = 16; o > 0; o >>= 1)
            mx = fmaxf(mx, __shfl_xor_sync(0xffffffffu, mx, o));
        const float e0 = __expf(v0 - mx);
        const float e1 = __expf(v1 - mx);
        float ssum = e0 + e1;
        #pragma unroll
        for (int o = 16; o > 0; o >>= 1)
            ssum += __shfl_xor_sync(0xffffffffu, ssum, o);
        const float inv = 1.f / ssum;
        ps[r * P_LD + lane]      = e0 * inv;
        ps[r * P_LD + lane + 32] = e1 * inv;
    }
    __syncthreads();

    // PV: thread handles (row, 4-col group); float4 V loads
    for (int it = tid; it < 64 * 20; it += 256) {
        const int r = it / 20, d4 = it % 20;
        const float* prow = &ps[r * P_LD];
        float4 acc = make_float4(0.f, 0.f, 0.f, 0.f);
        #pragma unroll 8
        for (int c = 0; c < WS_WIN; c++) {
            const float p = prow[c];
            const float4 v = *(const float4*)&vs[c * Q_LD + d4 * 4];
            acc.x = fmaf(p, v.x, acc.x);
            acc.y = fmaf(p, v.y, acc.y);
            acc.z = fmaf(p, v.z, acc.z);
            acc.w = fmaf(p, v.w, acc.w);
        }
        const size_t o = (size_t)(w * WS_WIN + r) * D_HID + h * HD_DIM + d4 * 4;
        const float vals[4] = {acc.x, acc.y, acc.z, acc.w};
        #pragma unroll
        for (int j = 0; j < 4; j++) {
            __nv_bfloat16 hh = __float2bfloat16(vals[j]);
            out_hi[o + j] = hh;
            out_lo[o + j] = __float2bfloat16(vals[j] - __bfloat162float(hh));
        }
    }
}

// ---------------------------------------------------------------------------
// launch
// ---------------------------------------------------------------------------
extern "C" void kernel_launch(void* const* d_in, const int* in_sizes, int n_in,
                              void* d_out, int out_size)
{
    (void)in_sizes; (void)n_in; (void)out_size;
    const float* hidden = (const float*)d_in[0];
    const float* masks  = (const float*)d_in[1];
    const float* cosv   = (const float*)d_in[2];
    const float* sinv   = (const float*)d_in[3];
    const float* qkv_w  = (const float*)d_in[4];
    const float* qkv_b  = (const float*)d_in[5];
    const float* proj_w = (const float*)d_in[6];
    const float* proj_b = (const float*)d_in[7];
    float* out = (float*)d_out;

    float* qkv_buf;
    __nv_bfloat16 *hid_hi, *hid_lo, *wqkv_hi, *wqkv_lo, *wproj_hi, *wproj_lo, *attn_hi, *attn_lo;
    cudaGetSymbolAddress((void**)&qkv_buf, g_qkv);
    cudaGetSymbolAddress((void**)&hid_hi, g_hid_hi);
    cudaGetSymbolAddress((void**)&hid_lo, g_hid_lo);
    cudaGetSymbolAddress((void**)&wqkv_hi, g_wqkv_hi);
    cudaGetSymbolAddress((void**)&wqkv_lo, g_wqkv_lo);
    cudaGetSymbolAddress((void**)&wproj_hi, g_wproj_hi);
    cudaGetSymbolAddress((void**)&wproj_lo, g_wproj_lo);
    cudaGetSymbolAddress((void**)&attn_hi, g_attn_hi);
    cudaGetSymbolAddress((void**)&attn_lo, g_attn_lo);

    // 0) fp32 -> bf16 hi/lo splits
    {
        int n1 = S_LEN * D_HID;
        split_bf16<<<(n1 + 255) / 256, 256>>>(hidden, hid_hi, hid_lo, n1);
        int n2 = QKV_N * D_HID;
        split_bf16<<<(n2 + 255) / 256, 256>>>(qkv_w, wqkv_hi, wqkv_lo, n2);
        int n3 = D_HID * D_HID;
        split_bf16<<<(n3 + 255) / 256, 256>>>(proj_w, wproj_hi, wproj_lo, n3);
    }

    // 1) QKV projection (mma.sync bf16x3)
    {
        cudaFuncSetAttribute(gemm_bf16x3, cudaFuncAttributeMaxDynamicSharedMemorySize, GEMM_SMEM);
        dim3 grid(QKV_N / BN, S_LEN / BM);
        gemm_bf16x3<<<grid, 512, GEMM_SMEM>>>(hid_hi, hid_lo, wqkv_hi, wqkv_lo,
                                              qkv_b, qkv_buf, QKV_N);
    }

    // 2) windowed attention with fused RoPE (fp32), emits bf16 hi/lo
    {
        const int smem = (3 * WS_WIN * Q_LD + WS_WIN * P_LD) * (int)sizeof(float);
        cudaFuncSetAttribute(attn_kernel, cudaFuncAttributeMaxDynamicSharedMemorySize, smem);
        attn_kernel<<<NW_WIN * H_NUM, 256, smem>>>(qkv_buf, masks, cosv, sinv, attn_hi, attn_lo);
    }

    // 3) output projection (mma.sync bf16x3)
    {
        dim3 grid(D_HID / BN, S_LEN / BM);
        gemm_bf16x3<<<grid, 512, GEMM_SMEM>>>(attn_hi, attn_lo, wproj_hi, wproj_lo,
                                              proj_b, out, D_HID);
    }
}

// round 7
// speedup vs baseline: 1.2078x; 1.2078x over previous
#include <cuda_runtime.h>
#include <cuda_bf16.h>
#include <cstdint>
#include <cstddef>

// ---------------------------------------------------------------------------
// Problem constants
// ---------------------------------------------------------------------------
#define S_LEN 16384
#define D_HID 1280
#define H_NUM 16
#define HD_DIM 80
#define WS_WIN 64
#define NW_WIN (S_LEN / WS_WIN)   // 256
#define QKV_N (3 * D_HID)         // 3840
#define KDIM 1280

// GEMM tiling: CTA 128x256, BK=32, 16 warps (2Mx8N), warp tile 64x32
#define BM 128
#define BN 256
#define BK 32
#define STAGES 3
#define KT_ITERS (KDIM / BK)      // 40
#define STAGE_BYTES 49152         // Ah 8K | Al 8K | Bh 16K | Bl 16K
#define GEMM_SMEM (STAGES * STAGE_BYTES)   // 147456

// ---------------------------------------------------------------------------
// Scratch (device globals: allocation-free contract)
// ---------------------------------------------------------------------------
__device__ float g_qkv[(size_t)S_LEN * QKV_N];
__device__ __nv_bfloat16 g_hid_hi[(size_t)S_LEN * D_HID];
__device__ __nv_bfloat16 g_hid_lo[(size_t)S_LEN * D_HID];
__device__ __nv_bfloat16 g_wqkv_hi[(size_t)QKV_N * D_HID];
__device__ __nv_bfloat16 g_wqkv_lo[(size_t)QKV_N * D_HID];
__device__ __nv_bfloat16 g_wproj_hi[(size_t)D_HID * D_HID];
__device__ __nv_bfloat16 g_wproj_lo[(size_t)D_HID * D_HID];
__device__ __nv_bfloat16 g_attn_hi[(size_t)S_LEN * D_HID];
__device__ __nv_bfloat16 g_attn_lo[(size_t)S_LEN * D_HID];

// ---------------------------------------------------------------------------
// PTX helpers (baseline sm_80+ only -- harness targets plain sm_100)
// ---------------------------------------------------------------------------
__device__ __forceinline__ uint32_t smem_u32(const void* p) {
    uint32_t a;
    asm("{ .reg .u64 t; cvta.to.shared.u64 t, %1; cvt.u32.u64 %0, t; }"
        : "=r"(a) : "l"(p));
    return a;
}

#define CP_ASYNC16(smem_addr, gptr) \
    asm volatile("cp.async.cg.shared.global [%0], [%1], 16;\n" \
                 :: "r"(smem_addr), "l"(gptr))
#define CP_ASYNC_COMMIT() asm volatile("cp.async.commit_group;\n" ::: "memory")
#define CP_ASYNC_WAIT1()  asm volatile("cp.async.wait_group 1;\n" ::: "memory")

#define LDSM_X4(r0, r1, r2, r3, addr) \
    asm volatile("ldmatrix.sync.aligned.m8n8.x4.shared.b16 {%0,%1,%2,%3}, [%4];" \
                 : "=r"(r0), "=r"(r1), "=r"(r2), "=r"(r3) : "r"(addr))

#define MMA16816(d, a0, a1, a2, a3, b0, b1) \
    asm volatile("mma.sync.aligned.m16n8k16.row.col.f32.bf16.bf16.f32 " \
                 "{%0,%1,%2,%3}, {%4,%5,%6,%7}, {%8,%9}, {%0,%1,%2,%3};" \
                 : "+f"((d)[0]), "+f"((d)[1]), "+f"((d)[2]), "+f"((d)[3]) \
                 : "r"(a0), "r"(a1), "r"(a2), "r"(a3), "r"(b0), "r"(b1))

// ---------------------------------------------------------------------------
// bf16x3 mma.sync GEMM: C[M, Ntot] = A[M,1280] * B[Ntot,1280]^T + bias
// 512 threads, 16 warps (2M x 8N), warp tile 64x32.  (unchanged from R6)
// ---------------------------------------------------------------------------
__global__ void __launch_bounds__(512, 1) gemm_bf16x3(
    const __nv_bfloat16* __restrict__ Ah, const __nv_bfloat16* __restrict__ Al,
    const __nv_bfloat16* __restrict__ Bh, const __nv_bfloat16* __restrict__ Bl,
    const float* __restrict__ bias, float* __restrict__ C, int Ntot)
{
    extern __shared__ char smem[];
    const uint32_t sb = smem_u32(smem);
    const int tid = threadIdx.x;
    const int wid = tid >> 5, lane = tid & 31;
    const int warp_m = wid & 1;
    const int warp_n = wid >> 1;
    const int m0 = blockIdx.y * BM;
    const int n0 = blockIdx.x * BN;

    const __nv_bfloat16* gptr[6];
    uint32_t soff[6];
    #pragma unroll
    for (int t = 0; t < 6; t++) {
        const int idx = tid + t * 512;
        const __nv_bfloat16* base;
        int row, c;
        uint32_t mbase;
        int r0;
        if (idx < 1024) {
            const int mat = idx >> 9;
            const int li = idx & 511;
            row = li >> 2; c = li & 3;
            base = mat ? Al : Ah;
            mbase = (uint32_t)(mat * 8192);
            r0 = m0 + row;
        } else {
            const int j = idx - 1024;
            const int mat = j >> 10;
            const int li = j & 1023;
            row = li >> 2; c = li & 3;
            base = mat ? Bl : Bh;
            mbase = (uint32_t)(16384 + mat * 16384);
            r0 = n0 + row;
        }
        gptr[t] = base + (size_t)r0 * KDIM + c * 8;
        soff[t] = mbase + (uint32_t)(row * 64 + ((c ^ ((row >> 1) & 3)) << 4));
    }

    #pragma unroll
    for (int s = 0; s < STAGES - 1; s++) {
        const int kb = s * BK;
        #pragma unroll
        for (int t = 0; t < 6; t++)
            CP_ASYNC16(sb + s * STAGE_BYTES + soff[t], gptr[t] + kb);
        CP_ASYNC_COMMIT();
    }

    const int row_in = lane & 15;
    const int csel = lane >> 4;
    uint32_t aOff[4], bOff[2];
    #pragma unroll
    for (int fm = 0; fm < 4; fm++) {
        const int r = warp_m * 64 + fm * 16 + row_in;
        aOff[fm] = (uint32_t)(r * 64 + (((uint32_t)csel ^ ((r >> 1) & 3)) << 4));
    }
    #pragma unroll
    for (int bt = 0; bt < 2; bt++) {
        const int r = warp_n * 32 + bt * 16 + row_in;
        bOff[bt] = (uint32_t)(16384 + r * 64 + (((uint32_t)csel ^ ((r >> 1) & 3)) << 4));
    }

    float acc[4][4][4];
    #pragma unroll
    for (int i = 0; i < 4; i++)
        #pragma unroll
        for (int j = 0; j < 4; j++)
            #pragma unroll
            for (int k = 0; k < 4; k++) acc[i][j][k] = 0.f;

    for (int kt = 0; kt < KT_ITERS; kt++) {
        CP_ASYNC_WAIT1();
        __syncthreads();

        if (kt + STAGES - 1 < KT_ITERS) {
            const int s = (kt + STAGES - 1) % STAGES;
            const int kb = (kt + STAGES - 1) * BK;
            #pragma unroll
            for (int t = 0; t < 6; t++)
                CP_ASYNC16(sb + s * STAGE_BYTES + soff[t], gptr[t] + kb);
        }
        CP_ASYNC_COMMIT();

        const uint32_t stg = sb + (kt % STAGES) * STAGE_BYTES;

        #pragma unroll
        for (int kk = 0; kk < 2; kk++) {
            const uint32_t kx = (uint32_t)(kk * 0x20);

            uint32_t bh[4][2], bl[4][2];
            #pragma unroll
            for (int bt = 0; bt < 2; bt++) {
                const uint32_t ad = stg + (bOff[bt] ^ kx);
                uint32_t r0, r1, r2, r3;
                LDSM_X4(r0, r1, r2, r3, ad);
                bh[bt * 2 + 0][0] = r0; bh[bt * 2 + 1][0] = r1;
                bh[bt * 2 + 0][1] = r2; bh[bt * 2 + 1][1] = r3;
                LDSM_X4(r0, r1, r2, r3, ad + 16384);
                bl[bt * 2 + 0][0] = r0; bl[bt * 2 + 1][0] = r1;
                bl[bt * 2 + 0][1] = r2; bl[bt * 2 + 1][1] = r3;
            }

            #pragma unroll
            for (int fm = 0; fm < 4; fm++) {
                const uint32_t ad = stg + (aOff[fm] ^ kx);
                uint32_t ah0, ah1, ah2, ah3, al0, al1, al2, al3;
                LDSM_X4(ah0, ah1, ah2, ah3, ad);
                LDSM_X4(al0, al1, al2, al3, ad + 8192);
                #pragma unroll
                for (int fn = 0; fn < 4; fn++)
                    MMA16816(acc[fm][fn], ah0, ah1, ah2, ah3, bh[fn][0], bh[fn][1]);
                #pragma unroll
                for (int fn = 0; fn < 4; fn++)
                    MMA16816(acc[fm][fn], ah0, ah1, ah2, ah3, bl[fn][0], bl[fn][1]);
                #pragma unroll
                for (int fn = 0; fn < 4; fn++)
                    MMA16816(acc[fm][fn], al0, al1, al2, al3, bh[fn][0], bh[fn][1]);
            }
        }
    }

    const int tr = lane >> 2;
    const int tc = (lane & 3) * 2;
    const int r_base = m0 + warp_m * 64;
    const int c_base = n0 + warp_n * 32;
    #pragma unroll
    for (int fn = 0; fn < 4; fn++) {
        const int col = c_base + fn * 8 + tc;
        const float2 bb = *(const float2*)&bias[col];
        #pragma unroll
        for (int fm = 0; fm < 4; fm++) {
            const int row0 = r_base + fm * 16 + tr;
            float2 v0, v1;
            v0.x = acc[fm][fn][0] + bb.x; v0.y = acc[fm][fn][1] + bb.y;
            v1.x = acc[fm][fn][2] + bb.x; v1.y = acc[fm][fn][3] + bb.y;
            *(float2*)&C[(size_t)row0 * Ntot + col] = v0;
            *(float2*)&C[(size_t)(row0 + 8) * Ntot + col] = v1;
        }
    }
}

// ---------------------------------------------------------------------------
// fp32 -> bf16 (hi, lo) split
// ---------------------------------------------------------------------------
__global__ void split_bf16(const float* __restrict__ src,
                           __nv_bfloat16* __restrict__ hi,
                           __nv_bfloat16* __restrict__ lo, int n)
{
    int i = blockIdx.x * blockDim.x + threadIdx.x;
    if (i < n) {
        float x = src[i];
        __nv_bfloat16 h = __float2bfloat16(x);
        hi[i] = h;
        lo[i] = __float2bfloat16(x - __bfloat162float(h));
    }
}

// ---------------------------------------------------------------------------
// Windowed attention v2 -- register-blocked, LDS-minimized.
// One block (256 thr) per (window, head). Warp w owns score/output rows 8w..8w+7.
// ---------------------------------------------------------------------------
#define Q_LD 84   // 336B rows: 16B-aligned, conflict-free for LDS.128 phases
#define P_LD 65

__global__ void __launch_bounds__(256) attn_kernel(
    const float* __restrict__ qkv,
    const float* __restrict__ mask,
    const float* __restrict__ cosv,
    const float* __restrict__ sinv,
    __nv_bfloat16* __restrict__ out_hi,
    __nv_bfloat16* __restrict__ out_lo)
{
    extern __shared__ float sm[];
    float* qs = sm;                    // 64 x 84
    float* ks = qs + 64 * Q_LD;
    float* vs = ks + 64 * Q_LD;
    float* ps = vs + 64 * Q_LD;        // 64 x 65

    const int w = blockIdx.x >> 4;
    const int h = blockIdx.x & 15;
    const int tid = threadIdx.x;
    const int warp = tid >> 5, lane = tid & 31;

    // ---- phase 1: load + fused RoPE (registers), V raw copy ----
    // items 0..639: q (p, d4 0..9); 640..1279: k; 1280..2559: v (p, c4 0..19)
    for (int u = tid; u < 2560; u += 256) {
        if (u < 1280) {
            const int mat = u >= 640;
            const int li = u - mat * 640;
            const int p = li / 10, d4 = (li % 10) * 4;
            const int s = w * WS_WIN + p;
            const float* src = qkv + (size_t)s * QKV_N + mat * D_HID + h * HD_DIM;
            const float4 a = *(const float4*)(src + d4);        // d in [0,40)
            const float4 b = *(const float4*)(src + d4 + 40);   // d in [40,80)
            const float4 c0 = *(const float4*)(cosv + s * HD_DIM + d4);
            const float4 c1 = *(const float4*)(cosv + s * HD_DIM + d4 + 40);
            const float4 s0 = *(const float4*)(sinv + s * HD_DIM + d4);
            const float4 s1 = *(const float4*)(sinv + s * HD_DIM + d4 + 40);
            float4 lo, hi;
            lo.x = a.x * c0.x - b.x * s0.x;  hi.x = b.x * c1.x + a.x * s1.x;
            lo.y = a.y * c0.y - b.y * s0.y;  hi.y = b.y * c1.y + a.y * s1.y;
            lo.z = a.z * c0.z - b.z * s0.z;  hi.z = b.z * c1.z + a.z * s1.z;
            lo.w = a.w * c0.w - b.w * s0.w;  hi.w = b.w * c1.w + a.w * s1.w;
            float* dst = (mat ? ks : qs) + p * Q_LD + d4;
            *(float4*)dst = lo;
            *(float4*)(dst + 40) = hi;
        } else {
            const int li = u - 1280;
            const int p = li / 20, c4 = (li % 20) * 4;
            const int s = w * WS_WIN + p;
            *(float4*)(vs + p * Q_LD + c4) =
                *(const float4*)(qkv + (size_t)s * QKV_N + 2 * D_HID + h * HD_DIM + c4);
        }
    }
    __syncthreads();

    // ---- QK^T: K loaded once per dd (regs), Q via broadcast LDS ----
    const int r0 = warp * 8;
    float v0[8], v1[8];
    #pragma unroll
    for (int i = 0; i < 8; i++) { v0[i] = 0.f; v1[i] = 0.f; }

    #pragma unroll 2
    for (int dd = 0; dd < 20; dd++) {
        const float4 ka = *(const float4*)&ks[lane * Q_LD + dd * 4];
        const float4 kb = *(const float4*)&ks[(lane + 32) * Q_LD + dd * 4];
        #pragma unroll
        for (int i = 0; i < 8; i++) {
            const float4 q = *(const float4*)&qs[(r0 + i) * Q_LD + dd * 4];
            v0[i] = fmaf(q.x, ka.x, v0[i]); v0[i] = fmaf(q.y, ka.y, v0[i]);
            v0[i] = fmaf(q.z, ka.z, v0[i]); v0[i] = fmaf(q.w, ka.w, v0[i]);
            v1[i] = fmaf(q.x, kb.x, v1[i]); v1[i] = fmaf(q.y, kb.y, v1[i]);
            v1[i] = fmaf(q.z, kb.z, v1[i]); v1[i] = fmaf(q.w, kb.w, v1[i]);
        }
    }

    // ---- softmax per row (warp-wide), P -> smem ----
    const float scale = 0.1118033988749895f;  // 1/sqrt(80)
    const float* mrow = mask + (size_t)w * (WS_WIN * WS_WIN);
    #pragma unroll
    for (int i = 0; i < 8; i++) {
        const int r = r0 + i;
        float a = v0[i] * scale + mrow[r * WS_WIN + lane];
        float b = v1[i] * scale + mrow[r * WS_WIN + lane + 32];
        float mx = fmaxf(a, b);
        #pragma unroll
        for (int o = 16; o > 0; o >>= 1)
            mx = fmaxf(mx, __shfl_xor_sync(0xffffffffu, mx, o));
        const float e0 = __expf(a - mx);
        const float e1 = __expf(b - mx);
        float ss = e0 + e1;
        #pragma unroll
        for (int o = 16; o > 0; o >>= 1)
            ss += __shfl_xor_sync(0xffffffffu, ss, o);
        const float inv = 1.f / ss;
        ps[r * P_LD + lane]      = e0 * inv;
        ps[r * P_LD + lane + 32] = e1 * inv;
    }
    __syncwarp();   // ps rows r0..r0+7 written/read by this warp only

    // ---- PV: lane owns cols {lane, lane+32, lane+64(<80)}; P via broadcast ----
    float acc0[8], acc1[8], acc2[8];
    #pragma unroll
    for (int i = 0; i < 8; i++) { acc0[i] = 0.f; acc1[i] = 0.f; acc2[i] = 0.f; }
    const bool has3 = (lane < 16);

    #pragma unroll 2
    for (int c = 0; c < 64; c++) {
        const float va = vs[c * Q_LD + lane];
        const float vb = vs[c * Q_LD + lane + 32];
        const float vc = has3 ? vs[c * Q_LD + lane + 64] : 0.f;
        #pragma unroll
        for (int i = 0; i < 8; i++) {
            const float p = ps[(r0 + i) * P_LD + c];
            acc0[i] = fmaf(p, va, acc0[i]);
            acc1[i] = fmaf(p, vb, acc1[i]);
            acc2[i] = fmaf(p, vc, acc2[i]);
        }
    }

    // ---- output: bf16 hi/lo ----
    #pragma unroll
    for (int i = 0; i < 8; i++) {
        const size_t o = (size_t)(w * WS_WIN + r0 + i) * D_HID + h * HD_DIM;
        {
            const __nv_bfloat16 hh = __float2bfloat16(acc0[i]);
            out_hi[o + lane] = hh;
            out_lo[o + lane] = __float2bfloat16(acc0[i] - __bfloat162float(hh));
        }
        {
            const __nv_bfloat16 hh = __float2bfloat16(acc1[i]);
            out_hi[o + lane + 32] = hh;
            out_lo[o + lane + 32] = __float2bfloat16(acc1[i] - __bfloat162float(hh));
        }
        if (has3) {
            const __nv_bfloat16 hh = __float2bfloat16(acc2[i]);
            out_hi[o + lane + 64] = hh;
            out_lo[o + lane + 64] = __float2bfloat16(acc2[i] - __bfloat162float(hh));
        }
    }
}

// ---------------------------------------------------------------------------
// launch
// ---------------------------------------------------------------------------
extern "C" void kernel_launch(void* const* d_in, const int* in_sizes, int n_in,
                              void* d_out, int out_size)
{
    (void)in_sizes; (void)n_in; (void)out_size;
    const float* hidden = (const float*)d_in[0];
    const float* masks  = (const float*)d_in[1];
    const float* cosv   = (const float*)d_in[2];
    const float* sinv   = (const float*)d_in[3];
    const float* qkv_w  = (const float*)d_in[4];
    const float* qkv_b  = (const float*)d_in[5];
    const float* proj_w = (const float*)d_in[6];
    const float* proj_b = (const float*)d_in[7];
    float* out = (float*)d_out;

    float* qkv_buf;
    __nv_bfloat16 *hid_hi, *hid_lo, *wqkv_hi, *wqkv_lo, *wproj_hi, *wproj_lo, *attn_hi, *attn_lo;
    cudaGetSymbolAddress((void**)&qkv_buf, g_qkv);
    cudaGetSymbolAddress((void**)&hid_hi, g_hid_hi);
    cudaGetSymbolAddress((void**)&hid_lo, g_hid_lo);
    cudaGetSymbolAddress((void**)&wqkv_hi, g_wqkv_hi);
    cudaGetSymbolAddress((void**)&wqkv_lo, g_wqkv_lo);
    cudaGetSymbolAddress((void**)&wproj_hi, g_wproj_hi);
    cudaGetSymbolAddress((void**)&wproj_lo, g_wproj_lo);
    cudaGetSymbolAddress((void**)&attn_hi, g_attn_hi);
    cudaGetSymbolAddress((void**)&attn_lo, g_attn_lo);

    // 0) fp32 -> bf16 hi/lo splits
    {
        int n1 = S_LEN * D_HID;
        split_bf16<<<(n1 + 255) / 256, 256>>>(hidden, hid_hi, hid_lo, n1);
        int n2 = QKV_N * D_HID;
        split_bf16<<<(n2 + 255) / 256, 256>>>(qkv_w, wqkv_hi, wqkv_lo, n2);
        int n3 = D_HID * D_HID;
        split_bf16<<<(n3 + 255) / 256, 256>>>(proj_w, wproj_hi, wproj_lo, n3);
    }

    // 1) QKV projection (mma.sync bf16x3)
    {
        cudaFuncSetAttribute(gemm_bf16x3, cudaFuncAttributeMaxDynamicSharedMemorySize, GEMM_SMEM);
        dim3 grid(QKV_N / BN, S_LEN / BM);
        gemm_bf16x3<<<grid, 512, GEMM_SMEM>>>(hid_hi, hid_lo, wqkv_hi, wqkv_lo,
                                              qkv_b, qkv_buf, QKV_N);
    }

    // 2) windowed attention v2 (fused RoPE, register-blocked), emits bf16 hi/lo
    {
        const int smem = (3 * WS_WIN * Q_LD + WS_WIN * P_LD) * (int)sizeof(float);
        cudaFuncSetAttribute(attn_kernel, cudaFuncAttributeMaxDynamicSharedMemorySize, smem);
        attn_kernel<<<NW_WIN * H_NUM, 256, smem>>>(qkv_buf, masks, cosv, sinv, attn_hi, attn_lo);
    }

    // 3) output projection (mma.sync bf16x3)
    {
        dim3 grid(D_HID / BN, S_LEN / BM);
        gemm_bf16x3<<<grid, 512, GEMM_SMEM>>>(attn_hi, attn_lo, wproj_hi, wproj_lo,
                                              proj_b, out, D_HID);
    }
}

// round 8
// speedup vs baseline: 1.9566x; 1.6201x over previous
#include <cuda_runtime.h>
#include <cuda_bf16.h>
#include <cstdint>
#include <cstddef>

// ---------------------------------------------------------------------------
// Problem constants
// ---------------------------------------------------------------------------
#define S_LEN 16384
#define D_HID 1280
#define H_NUM 16
#define HD_DIM 80
#define WS_WIN 64
#define NW_WIN (S_LEN / WS_WIN)   // 256
#define QKV_N (3 * D_HID)         // 3840
#define KDIM 1280

// GEMM tiling: CTA 128x256, BK=32 fp32, 16 warps (2Mx8N), warp tile 64x32
#define BM 128
#define BN 256
#define BK 32
#define STAGES 3
#define KT_ITERS (KDIM / BK)      // 40
#define STAGE_BYTES 49152         // A 16K (128x32 f32) | B 32K (256x32 f32)
#define GEMM_SMEM (STAGES * STAGE_BYTES)   // 147456

// ---------------------------------------------------------------------------
// Scratch (device globals: allocation-free contract)
// ---------------------------------------------------------------------------
__device__ float g_qkv[(size_t)S_LEN * QKV_N];     // fp32 qkv output
__device__ float g_hid_t[(size_t)S_LEN * D_HID];   // tf32-rounded hidden
__device__ float g_wqkv_t[(size_t)QKV_N * D_HID];  // tf32-rounded qkv weight
__device__ float g_wproj_t[(size_t)D_HID * D_HID]; // tf32-rounded proj weight
__device__ float g_attn_t[(size_t)S_LEN * D_HID];  // tf32-rounded attn output

// ---------------------------------------------------------------------------
// PTX helpers (baseline sm_80+ only -- harness targets plain sm_100)
// ---------------------------------------------------------------------------
__device__ __forceinline__ uint32_t smem_u32(const void* p) {
    uint32_t a;
    asm("{ .reg .u64 t; cvta.to.shared.u64 t, %1; cvt.u32.u64 %0, t; }"
        : "=r"(a) : "l"(p));
    return a;
}

__device__ __forceinline__ float to_tf32f(float x) {
    uint32_t v;
    asm("cvt.rna.tf32.f32 %0, %1;" : "=r"(v) : "f"(x));
    return __uint_as_float(v);
}

#define CP_ASYNC16(smem_addr, gptr) \
    asm volatile("cp.async.cg.shared.global [%0], [%1], 16;\n" \
                 :: "r"(smem_addr), "l"(gptr))
#define CP_ASYNC_COMMIT() asm volatile("cp.async.commit_group;\n" ::: "memory")
#define CP_ASYNC_WAIT1()  asm volatile("cp.async.wait_group 1;\n" ::: "memory")

#define LDSM_X4(r0, r1, r2, r3, addr) \
    asm volatile("ldmatrix.sync.aligned.m8n8.x4.shared.b16 {%0,%1,%2,%3}, [%4];" \
                 : "=r"(r0), "=r"(r1), "=r"(r2), "=r"(r3) : "r"(addr))

#define MMA_TF32(d, a0, a1, a2, a3, b0, b1) \
    asm volatile("mma.sync.aligned.m16n8k8.row.col.f32.tf32.tf32.f32 " \
                 "{%0,%1,%2,%3}, {%4,%5,%6,%7}, {%8,%9}, {%0,%1,%2,%3};" \
                 : "+f"((d)[0]), "+f"((d)[1]), "+f"((d)[2]), "+f"((d)[3]) \
                 : "r"(a0), "r"(a1), "r"(a2), "r"(a3), "r"(b0), "r"(b1))

// ---------------------------------------------------------------------------
// tf32 mma.sync GEMM: C[M, Ntot] = A[M,1280] * B[Ntot,1280]^T + bias
// A,B tf32-rounded fp32, K-major. 512 threads, 16 warps (2M x 8N), warp 64x32.
// smem stage: A[128][32 f32] @0 (128B rows), B[256][32 f32] @16384.
// Swizzle: 16B chunk c in [0,8) stored at c ^ (row & 7).
// ---------------------------------------------------------------------------
__global__ void __launch_bounds__(512, 1) gemm_tf32(
    const float* __restrict__ A, const float* __restrict__ B,
    const float* __restrict__ bias, float* __restrict__ C, int Ntot)
{
    extern __shared__ char smem[];
    const uint32_t sb = smem_u32(smem);
    const int tid = threadIdx.x;
    const int wid = tid >> 5, lane = tid & 31;
    const int warp_m = wid & 1;        // 0..1 (64-row slabs)
    const int warp_n = wid >> 1;       // 0..7 (32-col slabs)
    const int m0 = blockIdx.y * BM;
    const int n0 = blockIdx.x * BN;

    // ---- per-thread cp.async mapping: 6 chunks of 16B per stage ----
    // A: 1024 chunks (128 rows x 8/row), B: 2048 chunks (256 rows x 8/row)
    const float* gptr[6];
    uint32_t soff[6];
    #pragma unroll
    for (int t = 0; t < 6; t++) {
        const int idx = tid + t * 512;          // 0..3071
        int row, c;
        uint32_t mbase;
        const float* base;
        int r0;
        if (idx < 1024) {
            row = idx >> 3; c = idx & 7;
            base = A; mbase = 0; r0 = m0 + row;
        } else {
            const int j = idx - 1024;
            row = j >> 3; c = j & 7;
            base = B; mbase = 16384; r0 = n0 + row;
        }
        gptr[t] = base + (size_t)r0 * KDIM + c * 4;
        soff[t] = mbase + (uint32_t)(row * 128 + ((c ^ (row & 7)) << 4));
    }

    // ---- prefetch first STAGES-1 stages ----
    #pragma unroll
    for (int s = 0; s < STAGES - 1; s++) {
        const int kb = s * BK;
        #pragma unroll
        for (int t = 0; t < 6; t++)
            CP_ASYNC16(sb + s * STAGE_BYTES + soff[t], gptr[t] + kb);
        CP_ASYNC_COMMIT();
    }

    // ---- ldmatrix base offsets (k8s = 0), swizzled ----
    // A (16x8 tf32 = 16x16 b16 per fm): lanes 0-15 -> rows, lanes 16-31 -> 2nd chunk
    const int a_row = warp_m * 64 + (lane & 15);
    const int a_cs = lane >> 4;
    uint32_t aOff[4];
    #pragma unroll
    for (int fm = 0; fm < 4; fm++) {
        const int r = a_row + fm * 16;
        aOff[fm] = (uint32_t)(r * 128 + (((uint32_t)a_cs ^ (r & 7)) << 4));
    }
    // B pairs (2 n8 frags each): lane -> row (lane&7)+((lane>>4)<<3), chunkbit (lane>>3)&1
    const int b_row_in = (lane & 7) + ((lane >> 4) << 3);
    const int b_cs = (lane >> 3) & 1;
    uint32_t bOff[2];
    #pragma unroll
    for (int p = 0; p < 2; p++) {
        const int r = warp_n * 32 + p * 16 + b_row_in;
        bOff[p] = (uint32_t)(16384 + r * 128 + (((uint32_t)b_cs ^ (r & 7)) << 4));
    }

    float acc[4][4][4];
    #pragma unroll
    for (int i = 0; i < 4; i++)
        #pragma unroll
        for (int j = 0; j < 4; j++)
            #pragma unroll
            for (int k = 0; k < 4; k++) acc[i][j][k] = 0.f;

    // ---- main loop ----
    for (int kt = 0; kt < KT_ITERS; kt++) {
        CP_ASYNC_WAIT1();
        __syncthreads();

        if (kt + STAGES - 1 < KT_ITERS) {
            const int s = (kt + STAGES - 1) % STAGES;
            const int kb = (kt + STAGES - 1) * BK;
            #pragma unroll
            for (int t = 0; t < 6; t++)
                CP_ASYNC16(sb + s * STAGE_BYTES + soff[t], gptr[t] + kb);
        }
        CP_ASYNC_COMMIT();

        const uint32_t stg = sb + (kt % STAGES) * STAGE_BYTES;

        #pragma unroll
        for (int k8 = 0; k8 < 4; k8++) {
            const uint32_t kx = (uint32_t)(k8 << 5);   // chunk bits 1-2 -> addr bits 5-6

            // B: 2 x LDSM_X4 -> 4 n8 frags {b0,b1}
            uint32_t b[2][4];
            #pragma unroll
            for (int p = 0; p < 2; p++)
                LDSM_X4(b[p][0], b[p][1], b[p][2], b[p][3], stg + (bOff[p] ^ kx));

            #pragma unroll
            for (int fm = 0; fm < 4; fm++) {
                uint32_t a0, a1, a2, a3;
                LDSM_X4(a0, a1, a2, a3, stg + (aOff[fm] ^ kx));
                MMA_TF32(acc[fm][0], a0, a1, a2, a3, b[0][0], b[0][1]);
                MMA_TF32(acc[fm][1], a0, a1, a2, a3, b[0][2], b[0][3]);
                MMA_TF32(acc[fm][2], a0, a1, a2, a3, b[1][0], b[1][1]);
                MMA_TF32(acc[fm][3], a0, a1, a2, a3, b[1][2], b[1][3]);
            }
        }
    }

    // ---- epilogue: bias + coalesced STG.64 (m16n8 acc layout) ----
    const int tr = lane >> 2;
    const int tc = (lane & 3) * 2;
    const int r_base = m0 + warp_m * 64;
    const int c_base = n0 + warp_n * 32;
    #pragma unroll
    for (int fn = 0; fn < 4; fn++) {
        const int col = c_base + fn * 8 + tc;
        const float2 bb = *(const float2*)&bias[col];
        #pragma unroll
        for (int fm = 0; fm < 4; fm++) {
            const int row0 = r_base + fm * 16 + tr;
            float2 v0, v1;
            v0.x = acc[fm][fn][0] + bb.x; v0.y = acc[fm][fn][1] + bb.y;
            v1.x = acc[fm][fn][2] + bb.x; v1.y = acc[fm][fn][3] + bb.y;
            *(float2*)&C[(size_t)row0 * Ntot + col] = v0;
            *(float2*)&C[(size_t)(row0 + 8) * Ntot + col] = v1;
        }
    }
}

// ---------------------------------------------------------------------------
// fp32 -> tf32 (RNA) rounding prepass, float4-vectorized
// ---------------------------------------------------------------------------
__global__ void to_tf32(const float* __restrict__ src, float* __restrict__ dst, int n4)
{
    int i = blockIdx.x * blockDim.x + threadIdx.x;
    if (i < n4) {
        float4 v = ((const float4*)src)[i];
        v.x = to_tf32f(v.x); v.y = to_tf32f(v.y);
        v.z = to_tf32f(v.z); v.w = to_tf32f(v.w);
        ((float4*)dst)[i] = v;
    }
}

// ---------------------------------------------------------------------------
// Windowed attention (register-blocked, fused RoPE) -- unchanged from R7
// except the output is tf32-rounded fp32 into a single buffer.
// ---------------------------------------------------------------------------
#define Q_LD 84
#define P_LD 65

__global__ void __launch_bounds__(256) attn_kernel(
    const float* __restrict__ qkv,
    const float* __restrict__ mask,
    const float* __restrict__ cosv,
    const float* __restrict__ sinv,
    float* __restrict__ out_t)
{
    extern __shared__ float sm[];
    float* qs = sm;
    float* ks = qs + 64 * Q_LD;
    float* vs = ks + 64 * Q_LD;
    float* ps = vs + 64 * Q_LD;

    const int w = blockIdx.x >> 4;
    const int h = blockIdx.x & 15;
    const int tid = threadIdx.x;
    const int warp = tid >> 5, lane = tid & 31;

    // phase 1: load + fused RoPE (registers), V raw copy
    for (int u = tid; u < 2560; u += 256) {
        if (u < 1280) {
            const int mat = u >= 640;
            const int li = u - mat * 640;
            const int p = li / 10, d4 = (li % 10) * 4;
            const int s = w * WS_WIN + p;
            const float* src = qkv + (size_t)s * QKV_N + mat * D_HID + h * HD_DIM;
            const float4 a = *(const float4*)(src + d4);
            const float4 b = *(const float4*)(src + d4 + 40);
            const float4 c0 = *(const float4*)(cosv + s * HD_DIM + d4);
            const float4 c1 = *(const float4*)(cosv + s * HD_DIM + d4 + 40);
            const float4 s0 = *(const float4*)(sinv + s * HD_DIM + d4);
            const float4 s1 = *(const float4*)(sinv + s * HD_DIM + d4 + 40);
            float4 lo, hi;
            lo.x = a.x * c0.x - b.x * s0.x;  hi.x = b.x * c1.x + a.x * s1.x;
            lo.y = a.y * c0.y - b.y * s0.y;  hi.y = b.y * c1.y + a.y * s1.y;
            lo.z = a.z * c0.z - b.z * s0.z;  hi.z = b.z * c1.z + a.z * s1.z;
            lo.w = a.w * c0.w - b.w * s0.w;  hi.w = b.w * c1.w + a.w * s1.w;
            float* dst = (mat ? ks : qs) + p * Q_LD + d4;
            *(float4*)dst = lo;
            *(float4*)(dst + 40) = hi;
        } else {
            const int li = u - 1280;
            const int p = li / 20, c4 = (li % 20) * 4;
            const int s = w * WS_WIN + p;
            *(float4*)(vs + p * Q_LD + c4) =
                *(const float4*)(qkv + (size_t)s * QKV_N + 2 * D_HID + h * HD_DIM + c4);
        }
    }
    __syncthreads();

    // QK^T
    const int r0 = warp * 8;
    float v0[8], v1[8];
    #pragma unroll
    for (int i = 0; i < 8; i++) { v0[i] = 0.f; v1[i] = 0.f; }

    #pragma unroll 2
    for (int dd = 0; dd < 20; dd++) {
        const float4 ka = *(const float4*)&ks[lane * Q_LD + dd * 4];
        const float4 kb = *(const float4*)&ks[(lane + 32) * Q_LD + dd * 4];
        #pragma unroll
        for (int i = 0; i < 8; i++) {
            const float4 q = *(const float4*)&qs[(r0 + i) * Q_LD + dd * 4];
            v0[i] = fmaf(q.x, ka.x, v0[i]); v0[i] = fmaf(q.y, ka.y, v0[i]);
            v0[i] = fmaf(q.z, ka.z, v0[i]); v0[i] = fmaf(q.w, ka.w, v0[i]);
            v1[i] = fmaf(q.x, kb.x, v1[i]); v1[i] = fmaf(q.y, kb.y, v1[i]);
            v1[i] = fmaf(q.z, kb.z, v1[i]); v1[i] = fmaf(q.w, kb.w, v1[i]);
        }
    }

    // softmax
    const float scale = 0.1118033988749895f;
    const float* mrow = mask + (size_t)w * (WS_WIN * WS_WIN);
    #pragma unroll
    for (int i = 0; i < 8; i++) {
        const int r = r0 + i;
        float a = v0[i] * scale + mrow[r * WS_WIN + lane];
        float b = v1[i] * scale + mrow[r * WS_WIN + lane + 32];
        float mx = fmaxf(a, b);
        #pragma unroll
        for (int o = 16; o > 0; o >>= 1)
            mx = fmaxf(mx, __shfl_xor_sync(0xffffffffu, mx, o));
        const float e0 = __expf(a - mx);
        const float e1 = __expf(b - mx);
        float ss = e0 + e1;
        #pragma unroll
        for (int o = 16; o > 0; o >>= 1)
            ss += __shfl_xor_sync(0xffffffffu, ss, o);
        const float inv = 1.f / ss;
        ps[r * P_LD + lane]      = e0 * inv;
        ps[r * P_LD + lane + 32] = e1 * inv;
    }
    __syncwarp();

    // PV
    float acc0[8], acc1[8], acc2[8];
    #pragma unroll
    for (int i = 0; i < 8; i++) { acc0[i] = 0.f; acc1[i] = 0.f; acc2[i] = 0.f; }
    const bool has3 = (lane < 16);

    #pragma unroll 2
    for (int c = 0; c < 64; c++) {
        const float va = vs[c * Q_LD + lane];
        const float vb = vs[c * Q_LD + lane + 32];
        const float vc = has3 ? vs[c * Q_LD + lane + 64] : 0.f;
        #pragma unroll
        for (int i = 0; i < 8; i++) {
            const float p = ps[(r0 + i) * P_LD + c];
            acc0[i] = fmaf(p, va, acc0[i]);
            acc1[i] = fmaf(p, vb, acc1[i]);
            acc2[i] = fmaf(p, vc, acc2[i]);
        }
    }

    #pragma unroll
    for (int i = 0; i < 8; i++) {
        const size_t o = (size_t)(w * WS_WIN + r0 + i) * D_HID + h * HD_DIM;
        out_t[o + lane]      = to_tf32f(acc0[i]);
        out_t[o + lane + 32] = to_tf32f(acc1[i]);
        if (has3) out_t[o + lane + 64] = to_tf32f(acc2[i]);
    }
}

// ---------------------------------------------------------------------------
// launch
// ---------------------------------------------------------------------------
extern "C" void kernel_launch(void* const* d_in, const int* in_sizes, int n_in,
                              void* d_out, int out_size)
{
    (void)in_sizes; (void)n_in; (void)out_size;
    const float* hidden = (const float*)d_in[0];
    const float* masks  = (const float*)d_in[1];
    const float* cosv   = (const float*)d_in[2];
    const float* sinv   = (const float*)d_in[3];
    const float* qkv_w  = (const float*)d_in[4];
    const float* qkv_b  = (const float*)d_in[5];
    const float* proj_w = (const float*)d_in[6];
    const float* proj_b = (const float*)d_in[7];
    float* out = (float*)d_out;

    float *qkv_buf, *hid_t, *wqkv_t, *wproj_t, *attn_t;
    cudaGetSymbolAddress((void**)&qkv_buf, g_qkv);
    cudaGetSymbolAddress((void**)&hid_t, g_hid_t);
    cudaGetSymbolAddress((void**)&wqkv_t, g_wqkv_t);
    cudaGetSymbolAddress((void**)&wproj_t, g_wproj_t);
    cudaGetSymbolAddress((void**)&attn_t, g_attn_t);

    // 0) fp32 -> tf32 rounding prepasses
    {
        int n1 = (S_LEN * D_HID) / 4;
        to_tf32<<<(n1 + 255) / 256, 256>>>(hidden, hid_t, n1);
        int n2 = (QKV_N * D_HID) / 4;
        to_tf32<<<(n2 + 255) / 256, 256>>>(qkv_w, wqkv_t, n2);
        int n3 = (D_HID * D_HID) / 4;
        to_tf32<<<(n3 + 255) / 256, 256>>>(proj_w, wproj_t, n3);
    }

    // 1) QKV projection (mma.sync tf32): [S,1280] x [3840,1280]^T + b
    {
        cudaFuncSetAttribute(gemm_tf32, cudaFuncAttributeMaxDynamicSharedMemorySize, GEMM_SMEM);
        dim3 grid(QKV_N / BN, S_LEN / BM);
        gemm_tf32<<<grid, 512, GEMM_SMEM>>>(hid_t, wqkv_t, qkv_b, qkv_buf, QKV_N);
    }

    // 2) windowed attention (fused RoPE, register-blocked), emits tf32 fp32
    {
        const int smem = (3 * WS_WIN * Q_LD + WS_WIN * P_LD) * (int)sizeof(float);
        cudaFuncSetAttribute(attn_kernel, cudaFuncAttributeMaxDynamicSharedMemorySize, smem);
        attn_kernel<<<NW_WIN * H_NUM, 256, smem>>>(qkv_buf, masks, cosv, sinv, attn_t);
    }

    // 3) output projection (mma.sync tf32): [S,1280] x [1280,1280]^T + b
    {
        dim3 grid(D_HID / BN, S_LEN / BM);
        gemm_tf32<<<grid, 512, GEMM_SMEM>>>(attn_t, wproj_t, proj_b, out, D_HID);
    }
}

// round 9
// speedup vs baseline: 2.0507x; 1.0481x over previous
#include <cuda_runtime.h>
#include <cuda_bf16.h>
#include <cstdint>
#include <cstddef>

// ---------------------------------------------------------------------------
// Problem constants
// ---------------------------------------------------------------------------
#define S_LEN 16384
#define D_HID 1280
#define H_NUM 16
#define HD_DIM 80
#define WS_WIN 64
#define NW_WIN (S_LEN / WS_WIN)   // 256
#define QKV_N (3 * D_HID)         // 3840
#define KDIM 1280

// GEMM tiling: CTA 128x128, BK=32 fp32, 8 warps (2Mx4N), warp tile 64x32.
// 96KB smem/CTA + 128 regs/thread -> 2 CTAs per SM (cross-CTA barrier overlap).
#define BM 128
#define BN 128
#define BK 32
#define STAGES 3
#define KT_ITERS (KDIM / BK)      // 40
#define STAGE_BYTES 32768         // A 16K (128x32 f32) | B 16K (128x32 f32)
#define GEMM_SMEM (STAGES * STAGE_BYTES)   // 98304

// ---------------------------------------------------------------------------
// Scratch (device globals: allocation-free contract)
// ---------------------------------------------------------------------------
__device__ float g_qkv[(size_t)S_LEN * QKV_N];     // fp32 qkv output
__device__ float g_hid_t[(size_t)S_LEN * D_HID];   // tf32-rounded hidden
__device__ float g_wqkv_t[(size_t)QKV_N * D_HID];  // tf32-rounded qkv weight
__device__ float g_wproj_t[(size_t)D_HID * D_HID]; // tf32-rounded proj weight
__device__ float g_attn_t[(size_t)S_LEN * D_HID];  // tf32-rounded attn output

// ---------------------------------------------------------------------------
// PTX helpers (baseline sm_80+ only -- harness targets plain sm_100)
// ---------------------------------------------------------------------------
__device__ __forceinline__ uint32_t smem_u32(const void* p) {
    uint32_t a;
    asm("{ .reg .u64 t; cvta.to.shared.u64 t, %1; cvt.u32.u64 %0, t; }"
        : "=r"(a) : "l"(p));
    return a;
}

__device__ __forceinline__ float to_tf32f(float x) {
    uint32_t v;
    asm("cvt.rna.tf32.f32 %0, %1;" : "=r"(v) : "f"(x));
    return __uint_as_float(v);
}

#define CP_ASYNC16(smem_addr, gptr) \
    asm volatile("cp.async.cg.shared.global [%0], [%1], 16;\n" \
                 :: "r"(smem_addr), "l"(gptr))
#define CP_ASYNC_COMMIT() asm volatile("cp.async.commit_group;\n" ::: "memory")
#define CP_ASYNC_WAIT1()  asm volatile("cp.async.wait_group 1;\n" ::: "memory")

#define LDSM_X4(r0, r1, r2, r3, addr) \
    asm volatile("ldmatrix.sync.aligned.m8n8.x4.shared.b16 {%0,%1,%2,%3}, [%4];" \
                 : "=r"(r0), "=r"(r1), "=r"(r2), "=r"(r3) : "r"(addr))

#define MMA_TF32(d, a0, a1, a2, a3, b0, b1) \
    asm volatile("mma.sync.aligned.m16n8k8.row.col.f32.tf32.tf32.f32 " \
                 "{%0,%1,%2,%3}, {%4,%5,%6,%7}, {%8,%9}, {%0,%1,%2,%3};" \
                 : "+f"((d)[0]), "+f"((d)[1]), "+f"((d)[2]), "+f"((d)[3]) \
                 : "r"(a0), "r"(a1), "r"(a2), "r"(a3), "r"(b0), "r"(b1))

// ---------------------------------------------------------------------------
// tf32 mma.sync GEMM: C[M, Ntot] = A[M,1280] * B[Ntot,1280]^T + bias
// 256 threads, 8 warps (2M x 4N), warp tile 64x32, 2 CTAs/SM.
// smem stage: A[128][32 f32] @0 (128B rows), B[128][32 f32] @16384.
// Swizzle: 16B chunk c in [0,8) stored at c ^ (row & 7).
// ---------------------------------------------------------------------------
__global__ void __launch_bounds__(256, 2) gemm_tf32(
    const float* __restrict__ A, const float* __restrict__ B,
    const float* __restrict__ bias, float* __restrict__ C, int Ntot)
{
    extern __shared__ char smem[];
    const uint32_t sb = smem_u32(smem);
    const int tid = threadIdx.x;
    const int wid = tid >> 5, lane = tid & 31;
    const int warp_m = wid & 1;        // 0..1 (64-row slabs)
    const int warp_n = wid >> 1;       // 0..3 (32-col slabs)
    const int m0 = blockIdx.y * BM;
    const int n0 = blockIdx.x * BN;

    // ---- per-thread cp.async mapping: 8 chunks of 16B per stage ----
    // A: 1024 chunks (128 rows x 8/row), B: 1024 chunks
    const float* gptr[8];
    uint32_t soff[8];
    #pragma unroll
    for (int t = 0; t < 8; t++) {
        const int idx = tid + t * 256;          // 0..2047
        int row, c;
        uint32_t mbase;
        const float* base;
        int r0;
        if (idx < 1024) {
            row = idx >> 3; c = idx & 7;
            base = A; mbase = 0; r0 = m0 + row;
        } else {
            const int j = idx - 1024;
            row = j >> 3; c = j & 7;
            base = B; mbase = 16384; r0 = n0 + row;
        }
        gptr[t] = base + (size_t)r0 * KDIM + c * 4;
        soff[t] = mbase + (uint32_t)(row * 128 + ((c ^ (row & 7)) << 4));
    }

    // ---- prefetch first STAGES-1 stages ----
    #pragma unroll
    for (int s = 0; s < STAGES - 1; s++) {
        const int kb = s * BK;
        #pragma unroll
        for (int t = 0; t < 8; t++)
            CP_ASYNC16(sb + s * STAGE_BYTES + soff[t], gptr[t] + kb);
        CP_ASYNC_COMMIT();
    }

    // ---- ldmatrix base offsets (k8 = 0), swizzled ----
    const int a_row = warp_m * 64 + (lane & 15);
    const int a_cs = lane >> 4;
    uint32_t aOff[4];
    #pragma unroll
    for (int fm = 0; fm < 4; fm++) {
        const int r = a_row + fm * 16;
        aOff[fm] = (uint32_t)(r * 128 + (((uint32_t)a_cs ^ (r & 7)) << 4));
    }
    const int b_row_in = (lane & 7) + ((lane >> 4) << 3);
    const int b_cs = (lane >> 3) & 1;
    uint32_t bOff[2];
    #pragma unroll
    for (int p = 0; p < 2; p++) {
        const int r = warp_n * 32 + p * 16 + b_row_in;
        bOff[p] = (uint32_t)(16384 + r * 128 + (((uint32_t)b_cs ^ (r & 7)) << 4));
    }

    float acc[4][4][4];
    #pragma unroll
    for (int i = 0; i < 4; i++)
        #pragma unroll
        for (int j = 0; j < 4; j++)
            #pragma unroll
            for (int k = 0; k < 4; k++) acc[i][j][k] = 0.f;

    // ---- main loop ----
    for (int kt = 0; kt < KT_ITERS; kt++) {
        CP_ASYNC_WAIT1();
        __syncthreads();

        if (kt + STAGES - 1 < KT_ITERS) {
            const int s = (kt + STAGES - 1) % STAGES;
            const int kb = (kt + STAGES - 1) * BK;
            #pragma unroll
            for (int t = 0; t < 8; t++)
                CP_ASYNC16(sb + s * STAGE_BYTES + soff[t], gptr[t] + kb);
        }
        CP_ASYNC_COMMIT();

        const uint32_t stg = sb + (kt % STAGES) * STAGE_BYTES;

        #pragma unroll
        for (int k8 = 0; k8 < 4; k8++) {
            const uint32_t kx = (uint32_t)(k8 << 5);

            uint32_t b[2][4];
            #pragma unroll
            for (int p = 0; p < 2; p++)
                LDSM_X4(b[p][0], b[p][1], b[p][2], b[p][3], stg + (bOff[p] ^ kx));

            #pragma unroll
            for (int fm = 0; fm < 4; fm++) {
                uint32_t a0, a1, a2, a3;
                LDSM_X4(a0, a1, a2, a3, stg + (aOff[fm] ^ kx));
                MMA_TF32(acc[fm][0], a0, a1, a2, a3, b[0][0], b[0][1]);
                MMA_TF32(acc[fm][1], a0, a1, a2, a3, b[0][2], b[0][3]);
                MMA_TF32(acc[fm][2], a0, a1, a2, a3, b[1][0], b[1][1]);
                MMA_TF32(acc[fm][3], a0, a1, a2, a3, b[1][2], b[1][3]);
            }
        }
    }

    // ---- epilogue: bias + coalesced STG.64 ----
    const int tr = lane >> 2;
    const int tc = (lane & 3) * 2;
    const int r_base = m0 + warp_m * 64;
    const int c_base = n0 + warp_n * 32;
    #pragma unroll
    for (int fn = 0; fn < 4; fn++) {
        const int col = c_base + fn * 8 + tc;
        const float2 bb = *(const float2*)&bias[col];
        #pragma unroll
        for (int fm = 0; fm < 4; fm++) {
            const int row0 = r_base + fm * 16 + tr;
            float2 v0, v1;
            v0.x = acc[fm][fn][0] + bb.x; v0.y = acc[fm][fn][1] + bb.y;
            v1.x = acc[fm][fn][2] + bb.x; v1.y = acc[fm][fn][3] + bb.y;
            *(float2*)&C[(size_t)row0 * Ntot + col] = v0;
            *(float2*)&C[(size_t)(row0 + 8) * Ntot + col] = v1;
        }
    }
}

// ---------------------------------------------------------------------------
// fp32 -> tf32 (RNA) rounding prepass, float4-vectorized
// ---------------------------------------------------------------------------
__global__ void to_tf32(const float* __restrict__ src, float* __restrict__ dst, int n4)
{
    int i = blockIdx.x * blockDim.x + threadIdx.x;
    if (i < n4) {
        float4 v = ((const float4*)src)[i];
        v.x = to_tf32f(v.x); v.y = to_tf32f(v.y);
        v.z = to_tf32f(v.z); v.w = to_tf32f(v.w);
        ((float4*)dst)[i] = v;
    }
}

// ---------------------------------------------------------------------------
// Windowed attention (register-blocked, fused RoPE).
// PV uses float4 P-row broadcasts (4x fewer crossbar wavefronts).
// ---------------------------------------------------------------------------
#define Q_LD 84   // 336B rows, 16B aligned
#define P_LD 68   // 272B rows, 16B aligned (float4 loads at 4-col steps)

__global__ void __launch_bounds__(256) attn_kernel(
    const float* __restrict__ qkv,
    const float* __restrict__ mask,
    const float* __restrict__ cosv,
    const float* __restrict__ sinv,
    float* __restrict__ out_t)
{
    extern __shared__ float sm[];
    float* qs = sm;
    float* ks = qs + 64 * Q_LD;
    float* vs = ks + 64 * Q_LD;
    float* ps = vs + 64 * Q_LD;

    const int w = blockIdx.x >> 4;
    const int h = blockIdx.x & 15;
    const int tid = threadIdx.x;
    const int warp = tid >> 5, lane = tid & 31;

    // phase 1: load + fused RoPE (registers), V raw copy
    for (int u = tid; u < 2560; u += 256) {
        if (u < 1280) {
            const int mat = u >= 640;
            const int li = u - mat * 640;
            const int p = li / 10, d4 = (li % 10) * 4;
            const int s = w * WS_WIN + p;
            const float* src = qkv + (size_t)s * QKV_N + mat * D_HID + h * HD_DIM;
            const float4 a = *(const float4*)(src + d4);
            const float4 b = *(const float4*)(src + d4 + 40);
            const float4 c0 = *(const float4*)(cosv + s * HD_DIM + d4);
            const float4 c1 = *(const float4*)(cosv + s * HD_DIM + d4 + 40);
            const float4 s0 = *(const float4*)(sinv + s * HD_DIM + d4);
            const float4 s1 = *(const float4*)(sinv + s * HD_DIM + d4 + 40);
            float4 lo, hi;
            lo.x = a.x * c0.x - b.x * s0.x;  hi.x = b.x * c1.x + a.x * s1.x;
            lo.y = a.y * c0.y - b.y * s0.y;  hi.y = b.y * c1.y + a.y * s1.y;
            lo.z = a.z * c0.z - b.z * s0.z;  hi.z = b.z * c1.z + a.z * s1.z;
            lo.w = a.w * c0.w - b.w * s0.w;  hi.w = b.w * c1.w + a.w * s1.w;
            float* dst = (mat ? ks : qs) + p * Q_LD + d4;
            *(float4*)dst = lo;
            *(float4*)(dst + 40) = hi;
        } else {
            const int li = u - 1280;
            const int p = li / 20, c4 = (li % 20) * 4;
            const int s = w * WS_WIN + p;
            *(float4*)(vs + p * Q_LD + c4) =
                *(const float4*)(qkv + (size_t)s * QKV_N + 2 * D_HID + h * HD_DIM + c4);
        }
    }
    __syncthreads();

    // QK^T
    const int r0 = warp * 8;
    float v0[8], v1[8];
    #pragma unroll
    for (int i = 0; i < 8; i++) { v0[i] = 0.f; v1[i] = 0.f; }

    #pragma unroll 2
    for (int dd = 0; dd < 20; dd++) {
        const float4 ka = *(const float4*)&ks[lane * Q_LD + dd * 4];
        const float4 kb = *(const float4*)&ks[(lane + 32) * Q_LD + dd * 4];
        #pragma unroll
        for (int i = 0; i < 8; i++) {
            const float4 q = *(const float4*)&qs[(r0 + i) * Q_LD + dd * 4];
            v0[i] = fmaf(q.x, ka.x, v0[i]); v0[i] = fmaf(q.y, ka.y, v0[i]);
            v0[i] = fmaf(q.z, ka.z, v0[i]); v0[i] = fmaf(q.w, ka.w, v0[i]);
            v1[i] = fmaf(q.x, kb.x, v1[i]); v1[i] = fmaf(q.y, kb.y, v1[i]);
            v1[i] = fmaf(q.z, kb.z, v1[i]); v1[i] = fmaf(q.w, kb.w, v1[i]);
        }
    }

    // softmax
    const float scale = 0.1118033988749895f;
    const float* mrow = mask + (size_t)w * (WS_WIN * WS_WIN);
    #pragma unroll
    for (int i = 0; i < 8; i++) {
        const int r = r0 + i;
        float a = v0[i] * scale + mrow[r * WS_WIN + lane];
        float b = v1[i] * scale + mrow[r * WS_WIN + lane + 32];
        float mx = fmaxf(a, b);
        #pragma unroll
        for (int o = 16; o > 0; o >>= 1)
            mx = fmaxf(mx, __shfl_xor_sync(0xffffffffu, mx, o));
        const float e0 = __expf(a - mx);
        const float e1 = __expf(b - mx);
        float ss = e0 + e1;
        #pragma unroll
        for (int o = 16; o > 0; o >>= 1)
            ss += __shfl_xor_sync(0xffffffffu, ss, o);
        const float inv = 1.f / ss;
        ps[r * P_LD + lane]      = e0 * inv;
        ps[r * P_LD + lane + 32] = e1 * inv;
    }
    __syncwarp();

    // PV: lane owns cols {lane, lane+32, lane+64(<80)}; P float4 broadcasts
    float acc0[8], acc1[8], acc2[8];
    #pragma unroll
    for (int i = 0; i < 8; i++) { acc0[i] = 0.f; acc1[i] = 0.f; acc2[i] = 0.f; }
    const bool has3 = (lane < 16);

    for (int cb = 0; cb < 64; cb += 4) {
        float pr[8][4];
        #pragma unroll
        for (int i = 0; i < 8; i++)
            *(float4*)pr[i] = *(const float4*)&ps[(r0 + i) * P_LD + cb];
        #pragma unroll
        for (int j = 0; j < 4; j++) {
            const int c = cb + j;
            const float va = vs[c * Q_LD + lane];
            const float vb = vs[c * Q_LD + lane + 32];
            const float vc = has3 ? vs[c * Q_LD + lane + 64] : 0.f;
            #pragma unroll
            for (int i = 0; i < 8; i++) {
                acc0[i] = fmaf(pr[i][j], va, acc0[i]);
                acc1[i] = fmaf(pr[i][j], vb, acc1[i]);
                acc2[i] = fmaf(pr[i][j], vc, acc2[i]);
            }
        }
    }

    #pragma unroll
    for (int i = 0; i < 8; i++) {
        const size_t o = (size_t)(w * WS_WIN + r0 + i) * D_HID + h * HD_DIM;
        out_t[o + lane]      = to_tf32f(acc0[i]);
        out_t[o + lane + 32] = to_tf32f(acc1[i]);
        if (has3) out_t[o + lane + 64] = to_tf32f(acc2[i]);
    }
}

// ---------------------------------------------------------------------------
// launch
// ---------------------------------------------------------------------------
extern "C" void kernel_launch(void* const* d_in, const int* in_sizes, int n_in,
                              void* d_out, int out_size)
{
    (void)in_sizes; (void)n_in; (void)out_size;
    const float* hidden = (const float*)d_in[0];
    const float* masks  = (const float*)d_in[1];
    const float* cosv   = (const float*)d_in[2];
    const float* sinv   = (const float*)d_in[3];
    const float* qkv_w  = (const float*)d_in[4];
    const float* qkv_b  = (const float*)d_in[5];
    const float* proj_w = (const float*)d_in[6];
    const float* proj_b = (const float*)d_in[7];
    float* out = (float*)d_out;

    float *qkv_buf, *hid_t, *wqkv_t, *wproj_t, *attn_t;
    cudaGetSymbolAddress((void**)&qkv_buf, g_qkv);
    cudaGetSymbolAddress((void**)&hid_t, g_hid_t);
    cudaGetSymbolAddress((void**)&wqkv_t, g_wqkv_t);
    cudaGetSymbolAddress((void**)&wproj_t, g_wproj_t);
    cudaGetSymbolAddress((void**)&attn_t, g_attn_t);

    // 0) fp32 -> tf32 rounding prepasses
    {
        int n1 = (S_LEN * D_HID) / 4;
        to_tf32<<<(n1 + 255) / 256, 256>>>(hidden, hid_t, n1);
        int n2 = (QKV_N * D_HID) / 4;
        to_tf32<<<(n2 + 255) / 256, 256>>>(qkv_w, wqkv_t, n2);
        int n3 = (D_HID * D_HID) / 4;
        to_tf32<<<(n3 + 255) / 256, 256>>>(proj_w, wproj_t, n3);
    }

    // 1) QKV projection (mma.sync tf32): [S,1280] x [3840,1280]^T + b
    {
        cudaFuncSetAttribute(gemm_tf32, cudaFuncAttributeMaxDynamicSharedMemorySize, GEMM_SMEM);
        dim3 grid(QKV_N / BN, S_LEN / BM);
        gemm_tf32<<<grid, 256, GEMM_SMEM>>>(hid_t, wqkv_t, qkv_b, qkv_buf, QKV_N);
    }

    // 2) windowed attention (fused RoPE, register-blocked), emits tf32 fp32
    {
        const int smem = (3 * WS_WIN * Q_LD + WS_WIN * P_LD) * (int)sizeof(float);
        cudaFuncSetAttribute(attn_kernel, cudaFuncAttributeMaxDynamicSharedMemorySize, smem);
        attn_kernel<<<NW_WIN * H_NUM, 256, smem>>>(qkv_buf, masks, cosv, sinv, attn_t);
    }

    // 3) output projection (mma.sync tf32): [S,1280] x [1280,1280]^T + b
    {
        dim3 grid(D_HID / BN, S_LEN / BM);
        gemm_tf32<<<grid, 256, GEMM_SMEM>>>(attn_t, wproj_t, proj_b, out, D_HID);
    }
}

// round 10
// speedup vs baseline: 2.1298x; 1.0386x over previous
#include <cuda_runtime.h>
#include <cuda_bf16.h>
#include <cstdint>
#include <cstddef>

// ---------------------------------------------------------------------------
// Problem constants
// ---------------------------------------------------------------------------
#define S_LEN 16384
#define D_HID 1280
#define H_NUM 16
#define HD_DIM 80
#define WS_WIN 64
#define NW_WIN (S_LEN / WS_WIN)   // 256
#define QKV_N (3 * D_HID)         // 3840
#define KDIM 1280

// GEMM tiling: CTA 128x128, BK=32 fp32, 8 warps (2Mx4N), warp tile 64x32.
#define BM 128
#define BN 128
#define BK 32
#define STAGES 3
#define KT_ITERS (KDIM / BK)      // 40
#define STAGE_BYTES 32768         // A 16K | B 16K
#define GEMM_SMEM (STAGES * STAGE_BYTES)   // 98304

// ---------------------------------------------------------------------------
// Scratch (device globals: allocation-free contract)
// ---------------------------------------------------------------------------
__device__ float g_qkv[(size_t)S_LEN * QKV_N];     // fp32 qkv output
__device__ float g_hid_t[(size_t)S_LEN * D_HID];   // tf32-rounded hidden
__device__ float g_wqkv_t[(size_t)QKV_N * D_HID];  // tf32-rounded qkv weight
__device__ float g_wproj_t[(size_t)D_HID * D_HID]; // tf32-rounded proj weight
__device__ float g_attn_t[(size_t)S_LEN * D_HID];  // tf32-rounded attn output

// ---------------------------------------------------------------------------
// PTX helpers (baseline sm_80+ only -- harness targets plain sm_100)
// ---------------------------------------------------------------------------
__device__ __forceinline__ uint32_t smem_u32(const void* p) {
    uint32_t a;
    asm("{ .reg .u64 t; cvta.to.shared.u64 t, %1; cvt.u32.u64 %0, t; }"
        : "=r"(a) : "l"(p));
    return a;
}

__device__ __forceinline__ float to_tf32f(float x) {
    uint32_t v;
    asm("cvt.rna.tf32.f32 %0, %1;" : "=r"(v) : "f"(x));
    return __uint_as_float(v);
}

#define CP_ASYNC16(smem_addr, gptr) \
    asm volatile("cp.async.cg.shared.global [%0], [%1], 16;\n" \
                 :: "r"(smem_addr), "l"(gptr))
#define CP_ASYNC_COMMIT() asm volatile("cp.async.commit_group;\n" ::: "memory")
#define CP_ASYNC_WAIT1()  asm volatile("cp.async.wait_group 1;\n" ::: "memory")

#define LDSM_X4(r0, r1, r2, r3, addr) \
    asm volatile("ldmatrix.sync.aligned.m8n8.x4.shared.b16 {%0,%1,%2,%3}, [%4];" \
                 : "=r"(r0), "=r"(r1), "=r"(r2), "=r"(r3) : "r"(addr))

#define MMA_TF32(d, a0, a1, a2, a3, b0, b1) \
    asm volatile("mma.sync.aligned.m16n8k8.row.col.f32.tf32.tf32.f32 " \
                 "{%0,%1,%2,%3}, {%4,%5,%6,%7}, {%8,%9}, {%0,%1,%2,%3};" \
                 : "+f"((d)[0]), "+f"((d)[1]), "+f"((d)[2]), "+f"((d)[3]) \
                 : "r"(a0), "r"(a1), "r"(a2), "r"(a3), "r"(b0), "r"(b1))

// ---------------------------------------------------------------------------
// tf32 mma.sync GEMM: C[M, Ntot] = A[M,1280] * B[Ntot,1280]^T + bias
// 256 threads, 8 warps (2M x 4N), warp tile 64x32, 2 CTAs/SM.
// A-fragment ldmatrix pipelined 1 deep to hide short-scoreboard stalls.
// ---------------------------------------------------------------------------
__global__ void __launch_bounds__(256, 2) gemm_tf32(
    const float* __restrict__ A, const float* __restrict__ B,
    const float* __restrict__ bias, float* __restrict__ C, int Ntot)
{
    extern __shared__ char smem[];
    const uint32_t sb = smem_u32(smem);
    const int tid = threadIdx.x;
    const int wid = tid >> 5, lane = tid & 31;
    const int warp_m = wid & 1;
    const int warp_n = wid >> 1;
    const int m0 = blockIdx.y * BM;
    const int n0 = blockIdx.x * BN;

    // ---- per-thread cp.async mapping: 8 chunks of 16B per stage ----
    const float* gptr[8];
    uint32_t soff[8];
    #pragma unroll
    for (int t = 0; t < 8; t++) {
        const int idx = tid + t * 256;
        int row, c;
        uint32_t mbase;
        const float* base;
        int r0;
        if (idx < 1024) {
            row = idx >> 3; c = idx & 7;
            base = A; mbase = 0; r0 = m0 + row;
        } else {
            const int j = idx - 1024;
            row = j >> 3; c = j & 7;
            base = B; mbase = 16384; r0 = n0 + row;
        }
        gptr[t] = base + (size_t)r0 * KDIM + c * 4;
        soff[t] = mbase + (uint32_t)(row * 128 + ((c ^ (row & 7)) << 4));
    }

    #pragma unroll
    for (int s = 0; s < STAGES - 1; s++) {
        const int kb = s * BK;
        #pragma unroll
        for (int t = 0; t < 8; t++)
            CP_ASYNC16(sb + s * STAGE_BYTES + soff[t], gptr[t] + kb);
        CP_ASYNC_COMMIT();
    }

    // ---- ldmatrix base offsets (k8 = 0), swizzled ----
    const int a_row = warp_m * 64 + (lane & 15);
    const int a_cs = lane >> 4;
    uint32_t aOff[4];
    #pragma unroll
    for (int fm = 0; fm < 4; fm++) {
        const int r = a_row + fm * 16;
        aOff[fm] = (uint32_t)(r * 128 + (((uint32_t)a_cs ^ (r & 7)) << 4));
    }
    const int b_row_in = (lane & 7) + ((lane >> 4) << 3);
    const int b_cs = (lane >> 3) & 1;
    uint32_t bOff[2];
    #pragma unroll
    for (int p = 0; p < 2; p++) {
        const int r = warp_n * 32 + p * 16 + b_row_in;
        bOff[p] = (uint32_t)(16384 + r * 128 + (((uint32_t)b_cs ^ (r & 7)) << 4));
    }

    float acc[4][4][4];
    #pragma unroll
    for (int i = 0; i < 4; i++)
        #pragma unroll
        for (int j = 0; j < 4; j++)
            #pragma unroll
            for (int k = 0; k < 4; k++) acc[i][j][k] = 0.f;

    // ---- main loop ----
    for (int kt = 0; kt < KT_ITERS; kt++) {
        CP_ASYNC_WAIT1();
        __syncthreads();

        if (kt + STAGES - 1 < KT_ITERS) {
            const int s = (kt + STAGES - 1) % STAGES;
            const int kb = (kt + STAGES - 1) * BK;
            #pragma unroll
            for (int t = 0; t < 8; t++)
                CP_ASYNC16(sb + s * STAGE_BYTES + soff[t], gptr[t] + kb);
        }
        CP_ASYNC_COMMIT();

        const uint32_t stg = sb + (kt % STAGES) * STAGE_BYTES;

        #pragma unroll
        for (int k8 = 0; k8 < 4; k8++) {
            const uint32_t kx = (uint32_t)(k8 << 5);

            // B fragments first (2 LDSM), then A pipelined 1 deep
            uint32_t b[2][4];
            LDSM_X4(b[0][0], b[0][1], b[0][2], b[0][3], stg + (bOff[0] ^ kx));
            LDSM_X4(b[1][0], b[1][1], b[1][2], b[1][3], stg + (bOff[1] ^ kx));

            uint32_t a[2][4];
            LDSM_X4(a[0][0], a[0][1], a[0][2], a[0][3], stg + (aOff[0] ^ kx));
            #pragma unroll
            for (int fm = 0; fm < 4; fm++) {
                const int cur = fm & 1;
                if (fm < 3) {
                    const int nxt = cur ^ 1;
                    LDSM_X4(a[nxt][0], a[nxt][1], a[nxt][2], a[nxt][3],
                            stg + (aOff[fm + 1] ^ kx));
                }
                MMA_TF32(acc[fm][0], a[cur][0], a[cur][1], a[cur][2], a[cur][3],
                         b[0][0], b[0][1]);
                MMA_TF32(acc[fm][1], a[cur][0], a[cur][1], a[cur][2], a[cur][3],
                         b[0][2], b[0][3]);
                MMA_TF32(acc[fm][2], a[cur][0], a[cur][1], a[cur][2], a[cur][3],
                         b[1][0], b[1][1]);
                MMA_TF32(acc[fm][3], a[cur][0], a[cur][1], a[cur][2], a[cur][3],
                         b[1][2], b[1][3]);
            }
        }
    }

    // ---- epilogue: bias + coalesced STG.64 ----
    const int tr = lane >> 2;
    const int tc = (lane & 3) * 2;
    const int r_base = m0 + warp_m * 64;
    const int c_base = n0 + warp_n * 32;
    #pragma unroll
    for (int fn = 0; fn < 4; fn++) {
        const int col = c_base + fn * 8 + tc;
        const float2 bb = *(const float2*)&bias[col];
        #pragma unroll
        for (int fm = 0; fm < 4; fm++) {
            const int row0 = r_base + fm * 16 + tr;
            float2 v0, v1;
            v0.x = acc[fm][fn][0] + bb.x; v0.y = acc[fm][fn][1] + bb.y;
            v1.x = acc[fm][fn][2] + bb.x; v1.y = acc[fm][fn][3] + bb.y;
            *(float2*)&C[(size_t)row0 * Ntot + col] = v0;
            *(float2*)&C[(size_t)(row0 + 8) * Ntot + col] = v1;
        }
    }
}

// ---------------------------------------------------------------------------
// fp32 -> tf32 (RNA) rounding prepass, float4-vectorized
// ---------------------------------------------------------------------------
__global__ void to_tf32(const float* __restrict__ src, float* __restrict__ dst, int n4)
{
    int i = blockIdx.x * blockDim.x + threadIdx.x;
    if (i < n4) {
        float4 v = ((const float4*)src)[i];
        v.x = to_tf32f(v.x); v.y = to_tf32f(v.y);
        v.z = to_tf32f(v.z); v.w = to_tf32f(v.w);
        ((float4*)dst)[i] = v;
    }
}

// ---------------------------------------------------------------------------
// Windowed attention (register-blocked, fused RoPE).
// P aliases Q's smem (each warp fully consumes its own 8 Q rows into
// registers before overwriting them with P) -> 63KB smem, 3 CTAs/SM.
// ---------------------------------------------------------------------------
#define Q_LD 84   // 336B rows, 16B aligned
#define ATTN_SMEM (3 * WS_WIN * Q_LD * (int)sizeof(float))   // 64512

__global__ void __launch_bounds__(256, 3) attn_kernel(
    const float* __restrict__ qkv,
    const float* __restrict__ mask,
    const float* __restrict__ cosv,
    const float* __restrict__ sinv,
    float* __restrict__ out_t)
{
    extern __shared__ float sm[];
    float* qs = sm;                    // 64 x 84
    float* ks = qs + 64 * Q_LD;
    float* vs = ks + 64 * Q_LD;
    float* ps = qs;                    // alias: P overwrites Q (same stride)

    const int w = blockIdx.x >> 4;
    const int h = blockIdx.x & 15;
    const int tid = threadIdx.x;
    const int warp = tid >> 5, lane = tid & 31;

    // phase 1: load + fused RoPE (registers), V raw copy
    for (int u = tid; u < 2560; u += 256) {
        if (u < 1280) {
            const int mat = u >= 640;
            const int li = u - mat * 640;
            const int p = li / 10, d4 = (li % 10) * 4;
            const int s = w * WS_WIN + p;
            const float* src = qkv + (size_t)s * QKV_N + mat * D_HID + h * HD_DIM;
            const float4 a = *(const float4*)(src + d4);
            const float4 b = *(const float4*)(src + d4 + 40);
            const float4 c0 = *(const float4*)(cosv + s * HD_DIM + d4);
            const float4 c1 = *(const float4*)(cosv + s * HD_DIM + d4 + 40);
            const float4 s0 = *(const float4*)(sinv + s * HD_DIM + d4);
            const float4 s1 = *(const float4*)(sinv + s * HD_DIM + d4 + 40);
            float4 lo, hi;
            lo.x = a.x * c0.x - b.x * s0.x;  hi.x = b.x * c1.x + a.x * s1.x;
            lo.y = a.y * c0.y - b.y * s0.y;  hi.y = b.y * c1.y + a.y * s1.y;
            lo.z = a.z * c0.z - b.z * s0.z;  hi.z = b.z * c1.z + a.z * s1.z;
            lo.w = a.w * c0.w - b.w * s0.w;  hi.w = b.w * c1.w + a.w * s1.w;
            float* dst = (mat ? ks : qs) + p * Q_LD + d4;
            *(float4*)dst = lo;
            *(float4*)(dst + 40) = hi;
        } else {
            const int li = u - 1280;
            const int p = li / 20, c4 = (li % 20) * 4;
            const int s = w * WS_WIN + p;
            *(float4*)(vs + p * Q_LD + c4) =
                *(const float4*)(qkv + (size_t)s * QKV_N + 2 * D_HID + h * HD_DIM + c4);
        }
    }
    __syncthreads();

    // QK^T: K loaded once per dd (regs), Q via broadcast LDS
    const int r0 = warp * 8;
    float v0[8], v1[8];
    #pragma unroll
    for (int i = 0; i < 8; i++) { v0[i] = 0.f; v1[i] = 0.f; }

    #pragma unroll 2
    for (int dd = 0; dd < 20; dd++) {
        const float4 ka = *(const float4*)&ks[lane * Q_LD + dd * 4];
        const float4 kb = *(const float4*)&ks[(lane + 32) * Q_LD + dd * 4];
        #pragma unroll
        for (int i = 0; i < 8; i++) {
            const float4 q = *(const float4*)&qs[(r0 + i) * Q_LD + dd * 4];
            v0[i] = fmaf(q.x, ka.x, v0[i]); v0[i] = fmaf(q.y, ka.y, v0[i]);
            v0[i] = fmaf(q.z, ka.z, v0[i]); v0[i] = fmaf(q.w, ka.w, v0[i]);
            v1[i] = fmaf(q.x, kb.x, v1[i]); v1[i] = fmaf(q.y, kb.y, v1[i]);
            v1[i] = fmaf(q.z, kb.z, v1[i]); v1[i] = fmaf(q.w, kb.w, v1[i]);
        }
    }

    // softmax; P written over this warp's own Q rows
    const float scale = 0.1118033988749895f;
    const float* mrow = mask + (size_t)w * (WS_WIN * WS_WIN);
    #pragma unroll
    for (int i = 0; i < 8; i++) {
        const int r = r0 + i;
        float a = v0[i] * scale + mrow[r * WS_WIN + lane];
        float b = v1[i] * scale + mrow[r * WS_WIN + lane + 32];
        float mx = fmaxf(a, b);
        #pragma unroll
        for (int o = 16; o > 0; o >>= 1)
            mx = fmaxf(mx, __shfl_xor_sync(0xffffffffu, mx, o));
        const float e0 = __expf(a - mx);
        const float e1 = __expf(b - mx);
        float ss = e0 + e1;
        #pragma unroll
        for (int o = 16; o > 0; o >>= 1)
            ss += __shfl_xor_sync(0xffffffffu, ss, o);
        const float inv = 1.f / ss;
        ps[r * Q_LD + lane]      = e0 * inv;
        ps[r * Q_LD + lane + 32] = e1 * inv;
    }
    __syncwarp();

    // PV: lane owns cols {lane, lane+32, lane+64(<80)}; P float2 broadcasts
    float acc0[8], acc1[8], acc2[8];
    #pragma unroll
    for (int i = 0; i < 8; i++) { acc0[i] = 0.f; acc1[i] = 0.f; acc2[i] = 0.f; }
    const bool has3 = (lane < 16);

    for (int cb = 0; cb < 64; cb += 2) {
        float pr[8][2];
        #pragma unroll
        for (int i = 0; i < 8; i++)
            *(float2*)pr[i] = *(const float2*)&ps[(r0 + i) * Q_LD + cb];
        #pragma unroll
        for (int j = 0; j < 2; j++) {
            const int c = cb + j;
            const float va = vs[c * Q_LD + lane];
            const float vb = vs[c * Q_LD + lane + 32];
            const float vc = has3 ? vs[c * Q_LD + lane + 64] : 0.f;
            #pragma unroll
            for (int i = 0; i < 8; i++) {
                acc0[i] = fmaf(pr[i][j], va, acc0[i]);
                acc1[i] = fmaf(pr[i][j], vb, acc1[i]);
                acc2[i] = fmaf(pr[i][j], vc, acc2[i]);
            }
        }
    }

    #pragma unroll
    for (int i = 0; i < 8; i++) {
        const size_t o = (size_t)(w * WS_WIN + r0 + i) * D_HID + h * HD_DIM;
        out_t[o + lane]      = to_tf32f(acc0[i]);
        out_t[o + lane + 32] = to_tf32f(acc1[i]);
        if (has3) out_t[o + lane + 64] = to_tf32f(acc2[i]);
    }
}

// ---------------------------------------------------------------------------
// launch
// ---------------------------------------------------------------------------
extern "C" void kernel_launch(void* const* d_in, const int* in_sizes, int n_in,
                              void* d_out, int out_size)
{
    (void)in_sizes; (void)n_in; (void)out_size;
    const float* hidden = (const float*)d_in[0];
    const float* masks  = (const float*)d_in[1];
    const float* cosv   = (const float*)d_in[2];
    const float* sinv   = (const float*)d_in[3];
    const float* qkv_w  = (const float*)d_in[4];
    const float* qkv_b  = (const float*)d_in[5];
    const float* proj_w = (const float*)d_in[6];
    const float* proj_b = (const float*)d_in[7];
    float* out = (float*)d_out;

    float *qkv_buf, *hid_t, *wqkv_t, *wproj_t, *attn_t;
    cudaGetSymbolAddress((void**)&qkv_buf, g_qkv);
    cudaGetSymbolAddress((void**)&hid_t, g_hid_t);
    cudaGetSymbolAddress((void**)&wqkv_t, g_wqkv_t);
    cudaGetSymbolAddress((void**)&wproj_t, g_wproj_t);
    cudaGetSymbolAddress((void**)&attn_t, g_attn_t);

    // 0) fp32 -> tf32 rounding prepasses
    {
        int n1 = (S_LEN * D_HID) / 4;
        to_tf32<<<(n1 + 255) / 256, 256>>>(hidden, hid_t, n1);
        int n2 = (QKV_N * D_HID) / 4;
        to_tf32<<<(n2 + 255) / 256, 256>>>(qkv_w, wqkv_t, n2);
        int n3 = (D_HID * D_HID) / 4;
        to_tf32<<<(n3 + 255) / 256, 256>>>(proj_w, wproj_t, n3);
    }

    // 1) QKV projection (mma.sync tf32): [S,1280] x [3840,1280]^T + b
    {
        cudaFuncSetAttribute(gemm_tf32, cudaFuncAttributeMaxDynamicSharedMemorySize, GEMM_SMEM);
        dim3 grid(QKV_N / BN, S_LEN / BM);
        gemm_tf32<<<grid, 256, GEMM_SMEM>>>(hid_t, wqkv_t, qkv_b, qkv_buf, QKV_N);
    }

    // 2) windowed attention (fused RoPE, register-blocked, P aliases Q)
    {
        cudaFuncSetAttribute(attn_kernel, cudaFuncAttributeMaxDynamicSharedMemorySize, ATTN_SMEM);
        attn_kernel<<<NW_WIN * H_NUM, 256, ATTN_SMEM>>>(qkv_buf, masks, cosv, sinv, attn_t);
    }

    // 3) output projection (mma.sync tf32): [S,1280] x [1280,1280]^T + b
    {
        dim3 grid(D_HID / BN, S_LEN / BM);
        gemm_tf32<<<grid, 256, GEMM_SMEM>>>(attn_t, wproj_t, proj_b, out, D_HID);
    }
}